// round 8
// baseline (speedup 1.0000x reference)
#include <cuda_runtime.h>
#include <cuda_bf16.h>
#include <math.h>
#include <stdint.h>

// B=2, S=2048, D=1024, H=16, HD=64

// ---------------- scratch (device globals) ----------------
__device__ __nv_bfloat16 g_xhi[4194304], g_xlo[4194304];       // x split
__device__ __nv_bfloat16 g_wqt_hi[3145728], g_wqt_lo[3145728]; // Wqkv^T split
__device__ __nv_bfloat16 g_wpt_hi[1048576], g_wpt_lo[1048576]; // Wproj^T split
__device__ __nv_bfloat16 g_yhi[4194304], g_ylo[4194304];       // attn out split

__device__ __nv_bfloat16 g_qh[4194304], g_ql[4194304];         // q heads split
__device__ __nv_bfloat16 g_kh[4194304], g_kl[4194304];         // k heads split
__device__ __nv_bfloat16 g_vh[4194304], g_vl[4194304];         // v heads split

// ---------------- helpers ----------------
__device__ __forceinline__ uint32_t smem_u32(const void* p) {
    uint32_t a;
    asm("{ .reg .u64 t; cvta.to.shared.u64 t, %1; cvt.u32.u64 %0, t; }"
        : "=r"(a) : "l"(p));
    return a;
}

#define CP_ASYNC16(dst, src) \
    asm volatile("cp.async.cg.shared.global [%0], [%1], 16;" \
                 :: "r"(dst), "l"(src))
#define CP_COMMIT() asm volatile("cp.async.commit_group;" ::: "memory")
#define CP_WAIT(n)  asm volatile("cp.async.wait_group %0;" :: "n"(n) : "memory")

__device__ __forceinline__ void ldmx4(uint32_t* r, uint32_t addr) {
    asm volatile("ldmatrix.sync.aligned.m8n8.x4.shared.b16 {%0,%1,%2,%3}, [%4];"
                 : "=r"(r[0]), "=r"(r[1]), "=r"(r[2]), "=r"(r[3]) : "r"(addr));
}
__device__ __forceinline__ void ldmx4t(uint32_t* r, uint32_t addr) {
    asm volatile("ldmatrix.sync.aligned.m8n8.x4.trans.shared.b16 {%0,%1,%2,%3}, [%4];"
                 : "=r"(r[0]), "=r"(r[1]), "=r"(r[2]), "=r"(r[3]) : "r"(addr));
}
__device__ __forceinline__ void mma16816(float* d, const uint32_t* a,
                                         const uint32_t* b) {
    asm volatile(
        "mma.sync.aligned.m16n8k16.row.col.f32.bf16.bf16.f32 "
        "{%0,%1,%2,%3}, {%4,%5,%6,%7}, {%8,%9}, {%0,%1,%2,%3};"
        : "+f"(d[0]), "+f"(d[1]), "+f"(d[2]), "+f"(d[3])
        : "r"(a[0]), "r"(a[1]), "r"(a[2]), "r"(a[3]), "r"(b[0]), "r"(b[1]));
}

__device__ __forceinline__ void psplit(float a, float b,
                                       uint32_t& hi, uint32_t& lo) {
    __nv_bfloat16 ha = __float2bfloat16(a), hb = __float2bfloat16(b);
    __nv_bfloat16 la = __float2bfloat16(a - __bfloat162float(ha));
    __nv_bfloat16 lb = __float2bfloat16(b - __bfloat162float(hb));
    __nv_bfloat162 h2 = __halves2bfloat162(ha, hb);
    __nv_bfloat162 l2 = __halves2bfloat162(la, lb);
    hi = *reinterpret_cast<uint32_t*>(&h2);
    lo = *reinterpret_cast<uint32_t*>(&l2);
}

__device__ __forceinline__ void wsplit(__nv_bfloat16* hi, __nv_bfloat16* lo,
                                       size_t o, float a, float b) {
    __nv_bfloat16 ha = __float2bfloat16(a), hb = __float2bfloat16(b);
    __nv_bfloat16 la = __float2bfloat16(a - __bfloat162float(ha));
    __nv_bfloat16 lb = __float2bfloat16(b - __bfloat162float(hb));
    *reinterpret_cast<__nv_bfloat162*>(hi + o) = __halves2bfloat162(ha, hb);
    *reinterpret_cast<__nv_bfloat162*>(lo + o) = __halves2bfloat162(la, lb);
}

// ---------------------------------------------------------------------------
// Split-precision conversion kernels
// ---------------------------------------------------------------------------
__global__ __launch_bounds__(256) void convert_split(
    const float* __restrict__ in, __nv_bfloat16* __restrict__ hi,
    __nv_bfloat16* __restrict__ lo)
{
    int i = (blockIdx.x * blockDim.x + threadIdx.x) << 2;
    float4 v = *(const float4*)(in + i);
    wsplit(hi, lo, i, v.x, v.y);
    wsplit(hi, lo, i + 2, v.z, v.w);
}

// W[K][N] f32 -> Wt_hi/lo[N][K] bf16 (transpose + split)
__global__ __launch_bounds__(256) void transpose_split(
    const float* __restrict__ W, __nv_bfloat16* __restrict__ Thi,
    __nv_bfloat16* __restrict__ Tlo, int K, int N)
{
    __shared__ float t[32][33];
    int n0 = blockIdx.x << 5, k0 = blockIdx.y << 5;
    int tx = threadIdx.x, ty = threadIdx.y;   // 32 x 8
    #pragma unroll
    for (int i = 0; i < 4; i++)
        t[ty + 8 * i][tx] = W[(size_t)(k0 + ty + 8 * i) * N + n0 + tx];
    __syncthreads();
    #pragma unroll
    for (int i = 0; i < 4; i++) {
        float v = t[tx][ty + 8 * i];
        __nv_bfloat16 h = __float2bfloat16(v);
        __nv_bfloat16 l = __float2bfloat16(v - __bfloat162float(h));
        size_t o = (size_t)(n0 + ty + 8 * i) * K + k0 + tx;
        Thi[o] = h;
        Tlo[o] = l;
    }
}

// ---------------------------------------------------------------------------
// Split-bf16 GEMM via mma.sync. 128x128 CTA, 4 warps (2x2) of 64x64 tiles.
// mma:ldsm = 6:1 (was 4:1). QKV variant fuses bias+RoPE+scatter+split.
// ---------------------------------------------------------------------------
#define TILE_B 10240
#define STAGE_B 40960

__device__ __forceinline__ void gemm_load_chunk(
    uint32_t sst,
    const __nv_bfloat16* __restrict__ Ahi, const __nv_bfloat16* __restrict__ Alo,
    const __nv_bfloat16* __restrict__ Bhi, const __nv_bfloat16* __restrict__ Blo,
    int bm, int bn, int K, int k0, int tid)
{
    #pragma unroll
    for (int j = 0; j < 4; j++) {
        int u = tid + (j << 7);              // 0..511 (128 threads)
        int r = u >> 2;
        int c16 = (u & 3) << 4;
        uint32_t d = sst + (uint32_t)r * 80 + c16;
        size_t ga = ((size_t)(bm + r) * K + k0) * 2 + c16;
        size_t gb = ((size_t)(bn + r) * K + k0) * 2 + c16;
        CP_ASYNC16(d,               (const char*)Ahi + ga);
        CP_ASYNC16(d + TILE_B,      (const char*)Alo + ga);
        CP_ASYNC16(d + 2 * TILE_B,  (const char*)Bhi + gb);
        CP_ASYNC16(d + 3 * TILE_B,  (const char*)Blo + gb);
    }
}

template<bool QKV>
__global__ __launch_bounds__(128) void gemm_mma(
    const __nv_bfloat16* __restrict__ Ahi, const __nv_bfloat16* __restrict__ Alo,
    const __nv_bfloat16* __restrict__ Bhi, const __nv_bfloat16* __restrict__ Blo,
    const float* __restrict__ bias, float* __restrict__ C,
    int M, int N, int K,
    const float* __restrict__ cs, const float* __restrict__ sn,
    float* __restrict__ out_k, float* __restrict__ out_v,
    __nv_bfloat16* __restrict__ qhx, __nv_bfloat16* __restrict__ qlx,
    __nv_bfloat16* __restrict__ khx, __nv_bfloat16* __restrict__ klx,
    __nv_bfloat16* __restrict__ vhx, __nv_bfloat16* __restrict__ vlx)
{
    extern __shared__ char smem[];
    const uint32_t sb = smem_u32(smem);

    const int tid = threadIdx.x;
    const int wid = tid >> 5;
    const int lane = tid & 31;
    const int bm = blockIdx.y << 7, bn = blockIdx.x << 7;
    const int wm = (wid >> 1) << 6;          // 0 or 64
    const int wn = (wid & 1) << 6;           // 0 or 64

    float acc[4][8][4] = {};                 // [m16][n8][frag]

    gemm_load_chunk(sb, Ahi, Alo, Bhi, Blo, bm, bn, K, 0, tid);
    CP_COMMIT();

    const int nchunk = K >> 5;
    for (int c = 0; c < nchunk; c++) {
        const uint32_t st = sb + (uint32_t)(c & 1) * STAGE_B;
        if (c + 1 < nchunk) {
            gemm_load_chunk(sb + (uint32_t)((c + 1) & 1) * STAGE_B,
                            Ahi, Alo, Bhi, Blo, bm, bn, K, (c + 1) << 5, tid);
            CP_COMMIT();
            CP_WAIT(1);
        } else {
            CP_WAIT(0);
        }
        __syncthreads();

        #pragma unroll
        for (int ks = 0; ks < 2; ks++) {
            const int kb = ks << 5;
            // A fragments: 64 rows x k16, hi+lo
            uint32_t af[2][4][4];
            #pragma unroll
            for (int s = 0; s < 2; s++) {
                uint32_t abase = st + (uint32_t)s * TILE_B;
                #pragma unroll
                for (int mt = 0; mt < 4; mt++) {
                    uint32_t addr = abase
                        + (uint32_t)(wm + (mt << 4) + (lane & 15)) * 80
                        + kb + ((lane >> 4) << 4);
                    ldmx4(af[s][mt], addr);
                }
            }
            // B fragments in 2-group batches (limits live registers)
            #pragma unroll
            for (int gp = 0; gp < 2; gp++) {
                uint32_t bf[2][2][4];   // [split][g2][frag]
                #pragma unroll
                for (int s = 0; s < 2; s++) {
                    uint32_t bbase = st + (uint32_t)(2 + s) * TILE_B;
                    #pragma unroll
                    for (int g2 = 0; g2 < 2; g2++) {
                        int g = (gp << 1) + g2;
                        uint32_t nrow = wn + (g << 4) + (((lane >> 4) & 1) << 3)
                                      + (lane & 7);
                        uint32_t addr = bbase + nrow * 80 + kb
                                      + (((lane >> 3) & 1) << 4);
                        ldmx4(bf[s][g2], addr);
                    }
                }
                // pass-major: 16 independent accumulators per pass
                #pragma unroll
                for (int p = 0; p < 3; p++) {
                    const int sa = (p == 2) ? 1 : 0;
                    const int sbb = (p == 1) ? 1 : 0;
                    #pragma unroll
                    for (int mt = 0; mt < 4; mt++)
                        #pragma unroll
                        for (int g2 = 0; g2 < 2; g2++) {
                            int n8 = (gp << 2) + (g2 << 1);
                            mma16816(acc[mt][n8],     af[sa][mt], &bf[sbb][g2][0]);
                            mma16816(acc[mt][n8 + 1], af[sa][mt], &bf[sbb][g2][2]);
                        }
                }
            }
        }
        __syncthreads();
    }

    const int r0 = bm + wm + (lane >> 2);
    const int cc0 = bn + wn + ((lane & 3) << 1);

    if (!QKV) {
        #pragma unroll
        for (int mt = 0; mt < 4; mt++) {
            #pragma unroll
            for (int nt = 0; nt < 8; nt++) {
                int col = cc0 + (nt << 3);
                float b0 = bias[col], b1 = bias[col + 1];
                int ra = r0 + (mt << 4);
                float2 v0 = make_float2(acc[mt][nt][0] + b0, acc[mt][nt][1] + b1);
                float2 v1 = make_float2(acc[mt][nt][2] + b0, acc[mt][nt][3] + b1);
                *(float2*)&C[(size_t)ra * N + col] = v0;
                *(float2*)&C[(size_t)(ra + 8) * N + col] = v1;
            }
        }
    } else {
        // fused bias + RoPE + head scatter + hi/lo split
        const int region = bn >> 10;            // 0=q, 1=k, 2=v
        #pragma unroll
        for (int mt = 0; mt < 4; mt++) {
            #pragma unroll
            for (int rr = 0; rr < 2; rr++) {
                int row = r0 + (mt << 4) + (rr << 3);
                int s = row & 2047, bb = row >> 11;
                #pragma unroll
                for (int nt = 0; nt < 8; nt++) {
                    int col = cc0 + (nt << 3);
                    float2 bp = *(const float2*)&bias[col];
                    float v0 = acc[mt][nt][rr * 2]     + bp.x;
                    float v1 = acc[mt][nt][rr * 2 + 1] + bp.y;
                    int d = col - (region << 10);
                    int h = d >> 6, hd = d & 63;
                    size_t o = (((size_t)(bb * 16 + h)) * 2048 + s) * 64 + hd;
                    if (region == 2) {
                        wsplit(vhx, vlx, o, v0, v1);
                        *(float2*)&out_v[o] = make_float2(v0, v1);
                    } else {
                        float2 cp = *(const float2*)&cs[s * 64 + hd];
                        float2 sp = *(const float2*)&sn[s * 64 + hd];
                        float rv0 = v0 * cp.x - v1 * sp.x;
                        float rv1 = v1 * cp.y + v0 * sp.y;
                        if (region == 0) {
                            wsplit(qhx, qlx, o, rv0 * 0.125f, rv1 * 0.125f);
                        } else {
                            wsplit(khx, klx, o, rv0, rv1);
                            *(float2*)&out_k[o] = make_float2(rv0, rv1);
                        }
                    }
                }
            }
        }
    }
}

// ---------------------------------------------------------------------------
// Flash attention via mma.sync (unchanged from round 7)
// ---------------------------------------------------------------------------
#define AST 144
#define ASTG 36864

__global__ __launch_bounds__(256) void attn_mma(
    const __nv_bfloat16* __restrict__ qhi, const __nv_bfloat16* __restrict__ qlo,
    const __nv_bfloat16* __restrict__ khi, const __nv_bfloat16* __restrict__ klo,
    const __nv_bfloat16* __restrict__ vhi, const __nv_bfloat16* __restrict__ vlo,
    __nv_bfloat16* __restrict__ yhi, __nv_bfloat16* __restrict__ ylo)
{
    extern __shared__ char smx[];
    const uint32_t sb = smem_u32(smx);
    const int tid = threadIdx.x, wid = tid >> 5, lane = tid & 31;
    const int bh = blockIdx.y, q0 = blockIdx.x << 7;
    const uint32_t QH = sb + ASTG, QL = QH + 18432;

    const size_t hbase = (size_t)bh * 2048 * 64;
    const char* kh = (const char*)(khi + hbase);
    const char* kl = (const char*)(klo + hbase);
    const char* vh = (const char*)(vhi + hbase);
    const char* vl = (const char*)(vlo + hbase);

    {
        const char* qhg = (const char*)(qhi + hbase + (size_t)q0 * 64);
        const char* qlg = (const char*)(qlo + hbase + (size_t)q0 * 64);
        #pragma unroll
        for (int j = 0; j < 4; j++) {
            int u = tid + (j << 8); int r = u >> 3; int c = (u & 7) << 4;
            CP_ASYNC16(QH + r * AST + c, qhg + r * 128 + c);
            CP_ASYNC16(QL + r * AST + c, qlg + r * 128 + c);
        }
        CP_COMMIT();
    }
    {
        #pragma unroll
        for (int j = 0; j < 2; j++) {
            int u = tid + (j << 8); int r = u >> 3; int c = (u & 7) << 4;
            uint32_t d = sb + r * AST + c;
            int go = r * 128 + c;
            CP_ASYNC16(d, kh + go);         CP_ASYNC16(d + 9216, kl + go);
            CP_ASYNC16(d + 18432, vh + go); CP_ASYNC16(d + 27648, vl + go);
        }
        CP_COMMIT();
    }
    CP_WAIT(1);
    __syncthreads();

    uint32_t qfh[4][4], qfl[4][4];
    #pragma unroll
    for (int kt = 0; kt < 4; kt++) {
        uint32_t a = QH + (uint32_t)((wid << 4) + (lane & 15)) * AST
                   + (kt << 5) + ((lane >> 4) << 4);
        ldmx4(qfh[kt], a);
        ldmx4(qfl[kt], a + 18432);
    }
    __syncthreads();

    float m0 = -1e30f, m1 = -1e30f, l0 = 0.f, l1 = 0.f;
    float o[8][4] = {};

    for (int t = 0; t < 32; t++) {
        const uint32_t st = sb + (uint32_t)(t & 1) * ASTG;
        if (t + 1 < 32) {
            uint32_t dstg = sb + (uint32_t)((t + 1) & 1) * ASTG;
            size_t tb = (size_t)(t + 1) * 64 * 128;
            #pragma unroll
            for (int j = 0; j < 2; j++) {
                int u = tid + (j << 8); int r = u >> 3; int c = (u & 7) << 4;
                uint32_t d = dstg + r * AST + c;
                size_t go = tb + r * 128 + c;
                CP_ASYNC16(d, kh + go);         CP_ASYNC16(d + 9216, kl + go);
                CP_ASYNC16(d + 18432, vh + go); CP_ASYNC16(d + 27648, vl + go);
            }
            CP_COMMIT();
            CP_WAIT(1);
        } else {
            CP_WAIT(0);
        }
        __syncthreads();

        float sacc[8][4] = {};
        #pragma unroll
        for (int kt = 0; kt < 4; kt++) {
            #pragma unroll
            for (int gp = 0; gp < 2; gp++) {
                uint32_t kf[2][2][4];
                #pragma unroll
                for (int g2 = 0; g2 < 2; g2++) {
                    int g = (gp << 1) + g2;
                    uint32_t na = st
                        + (uint32_t)((g << 4) + (((lane >> 4) & 1) << 3) + (lane & 7)) * AST
                        + (kt << 5) + (((lane >> 3) & 1) << 4);
                    ldmx4(kf[0][g2], na);
                    ldmx4(kf[1][g2], na + 9216);
                }
                #pragma unroll
                for (int p = 0; p < 3; p++) {
                    const uint32_t* qa = (p == 2) ? qfl[kt] : qfh[kt];
                    const int sk = (p == 1) ? 1 : 0;
                    #pragma unroll
                    for (int g2 = 0; g2 < 2; g2++) {
                        int g = (gp << 1) + g2;
                        mma16816(sacc[2 * g],     qa, &kf[sk][g2][0]);
                        mma16816(sacc[2 * g + 1], qa, &kf[sk][g2][2]);
                    }
                }
            }
        }

        float mx0 = -1e30f, mx1 = -1e30f;
        #pragma unroll
        for (int n = 0; n < 8; n++) {
            mx0 = fmaxf(mx0, fmaxf(sacc[n][0], sacc[n][1]));
            mx1 = fmaxf(mx1, fmaxf(sacc[n][2], sacc[n][3]));
        }
        mx0 = fmaxf(mx0, __shfl_xor_sync(0xffffffffu, mx0, 1));
        mx0 = fmaxf(mx0, __shfl_xor_sync(0xffffffffu, mx0, 2));
        mx1 = fmaxf(mx1, __shfl_xor_sync(0xffffffffu, mx1, 1));
        mx1 = fmaxf(mx1, __shfl_xor_sync(0xffffffffu, mx1, 2));
        float nm0 = fmaxf(m0, mx0), nm1 = fmaxf(m1, mx1);
        float al0 = __expf(m0 - nm0), al1 = __expf(m1 - nm1);
        float rs0 = 0.f, rs1 = 0.f;
        #pragma unroll
        for (int n = 0; n < 8; n++) {
            sacc[n][0] = __expf(sacc[n][0] - nm0);
            sacc[n][1] = __expf(sacc[n][1] - nm0);
            sacc[n][2] = __expf(sacc[n][2] - nm1);
            sacc[n][3] = __expf(sacc[n][3] - nm1);
            rs0 += sacc[n][0] + sacc[n][1];
            rs1 += sacc[n][2] + sacc[n][3];
        }
        rs0 += __shfl_xor_sync(0xffffffffu, rs0, 1);
        rs0 += __shfl_xor_sync(0xffffffffu, rs0, 2);
        rs1 += __shfl_xor_sync(0xffffffffu, rs1, 1);
        rs1 += __shfl_xor_sync(0xffffffffu, rs1, 2);
        l0 = l0 * al0 + rs0; l1 = l1 * al1 + rs1;
        m0 = nm0; m1 = nm1;
        #pragma unroll
        for (int n = 0; n < 8; n++) {
            o[n][0] *= al0; o[n][1] *= al0;
            o[n][2] *= al1; o[n][3] *= al1;
        }

        #pragma unroll
        for (int kt = 0; kt < 4; kt++) {
            uint32_t ph[4], pl[4];
            psplit(sacc[2 * kt][0],     sacc[2 * kt][1],     ph[0], pl[0]);
            psplit(sacc[2 * kt][2],     sacc[2 * kt][3],     ph[1], pl[1]);
            psplit(sacc[2 * kt + 1][0], sacc[2 * kt + 1][1], ph[2], pl[2]);
            psplit(sacc[2 * kt + 1][2], sacc[2 * kt + 1][3], ph[3], pl[3]);
            #pragma unroll
            for (int gp = 0; gp < 2; gp++) {
                uint32_t vf[2][2][4];
                #pragma unroll
                for (int g2 = 0; g2 < 2; g2++) {
                    int g = (gp << 1) + g2;
                    uint32_t va = st + 18432
                        + (uint32_t)((kt << 4) + (lane & 7) + (((lane >> 3) & 1) << 3)) * AST
                        + (((g << 4) + (((lane >> 4) & 1) << 3)) << 1);
                    ldmx4t(vf[0][g2], va);
                    ldmx4t(vf[1][g2], va + 9216);
                }
                #pragma unroll
                for (int p = 0; p < 3; p++) {
                    const uint32_t* pa = (p == 2) ? pl : ph;
                    const int sv = (p == 1) ? 1 : 0;
                    #pragma unroll
                    for (int g2 = 0; g2 < 2; g2++) {
                        int g = (gp << 1) + g2;
                        mma16816(o[2 * g],     pa, &vf[sv][g2][0]);
                        mma16816(o[2 * g + 1], pa, &vf[sv][g2][2]);
                    }
                }
            }
        }
        __syncthreads();
    }

    float il0 = 1.f / l0, il1 = 1.f / l1;
    const int b = bh >> 4, h = bh & 15;
    const int r0 = b * 2048 + q0 + (wid << 4) + (lane >> 2);
    const int c0 = h * 64 + ((lane & 3) << 1);
    #pragma unroll
    for (int n = 0; n < 8; n++) {
        size_t o0 = (size_t)r0 * 1024 + c0 + (n << 3);
        wsplit(yhi, ylo, o0, o[n][0] * il0, o[n][1] * il0);
        wsplit(yhi, ylo, o0 + 8 * 1024, o[n][2] * il1, o[n][3] * il1);
    }
}

// ---------------------------------------------------------------------------
extern "C" void kernel_launch(void* const* d_in, const int* in_sizes, int n_in,
                              void* d_out, int out_size)
{
    const float* x     = (const float*)d_in[0];
    const float* cs    = (const float*)d_in[1];
    const float* sn    = (const float*)d_in[2];
    const float* Wqkv  = (const float*)d_in[3];
    const float* bqkv  = (const float*)d_in[4];
    const float* Wproj = (const float*)d_in[5];
    const float* bproj = (const float*)d_in[6];

    float* out   = (float*)d_out;
    float* out_y = out;
    float* out_k = out + (size_t)2 * 2048 * 1024;
    float* out_v = out_k + (size_t)2 * 16 * 2048 * 64;

    __nv_bfloat16 *xhi, *xlo, *wqh, *wql, *wph, *wpl, *yhi, *ylo;
    __nv_bfloat16 *qh, *ql, *kh, *kl, *vh, *vl;
    cudaGetSymbolAddress((void**)&xhi, g_xhi);
    cudaGetSymbolAddress((void**)&xlo, g_xlo);
    cudaGetSymbolAddress((void**)&wqh, g_wqt_hi);
    cudaGetSymbolAddress((void**)&wql, g_wqt_lo);
    cudaGetSymbolAddress((void**)&wph, g_wpt_hi);
    cudaGetSymbolAddress((void**)&wpl, g_wpt_lo);
    cudaGetSymbolAddress((void**)&yhi, g_yhi);
    cudaGetSymbolAddress((void**)&ylo, g_ylo);
    cudaGetSymbolAddress((void**)&qh, g_qh);
    cudaGetSymbolAddress((void**)&ql, g_ql);
    cudaGetSymbolAddress((void**)&kh, g_kh);
    cudaGetSymbolAddress((void**)&kl, g_kl);
    cudaGetSymbolAddress((void**)&vh, g_vh);
    cudaGetSymbolAddress((void**)&vl, g_vl);

    const int gemm_smem = 2 * STAGE_B;
    cudaFuncSetAttribute(gemm_mma<true>,
                         cudaFuncAttributeMaxDynamicSharedMemorySize, gemm_smem);
    cudaFuncSetAttribute(gemm_mma<false>,
                         cudaFuncAttributeMaxDynamicSharedMemorySize, gemm_smem);
    const int attn_smem = 2 * ASTG;
    cudaFuncSetAttribute(attn_mma,
                         cudaFuncAttributeMaxDynamicSharedMemorySize, attn_smem);

    // 0) split conversions
    convert_split<<<4096, 256>>>(x, xhi, xlo);
    transpose_split<<<dim3(96, 32), dim3(32, 8)>>>(Wqkv, wqh, wql, 1024, 3072);
    transpose_split<<<dim3(32, 32), dim3(32, 8)>>>(Wproj, wph, wpl, 1024, 1024);

    // 1) QKV GEMM + fused bias/RoPE/scatter/split
    gemm_mma<true><<<dim3(24, 32), 128, gemm_smem>>>(
        xhi, xlo, wqh, wql, bqkv, nullptr, 4096, 3072, 1024,
        cs, sn, out_k, out_v, qh, ql, kh, kl, vh, vl);

    // 2) Attention -> y splits
    attn_mma<<<dim3(16, 32), 256, attn_smem>>>(
        qh, ql, kh, kl, vh, vl, yhi, ylo);

    // 3) Projection
    gemm_mma<false><<<dim3(8, 32), 128, gemm_smem>>>(
        yhi, ylo, wph, wpl, bproj, out_y, 4096, 1024, 1024,
        nullptr, nullptr, nullptr, nullptr,
        nullptr, nullptr, nullptr, nullptr, nullptr, nullptr);
}

// round 9
// speedup vs baseline: 1.0054x; 1.0054x over previous
#include <cuda_runtime.h>
#include <cuda_bf16.h>
#include <math.h>
#include <stdint.h>

// B=2, S=2048, D=1024, H=16, HD=64

// ---------------- scratch (device globals) ----------------
__device__ __nv_bfloat16 g_xhi[4194304], g_xlo[4194304];       // x split
__device__ __nv_bfloat16 g_wqt_hi[3145728], g_wqt_lo[3145728]; // Wqkv^T split
__device__ __nv_bfloat16 g_wpt_hi[1048576], g_wpt_lo[1048576]; // Wproj^T split
__device__ __nv_bfloat16 g_yhi[4194304], g_ylo[4194304];       // attn out split

__device__ __nv_bfloat16 g_qh[4194304], g_ql[4194304];         // q heads split
__device__ __nv_bfloat16 g_kh[4194304], g_kl[4194304];         // k heads split
__device__ __nv_bfloat16 g_vh[4194304], g_vl[4194304];         // v heads split

// ---------------- helpers ----------------
__device__ __forceinline__ uint32_t smem_u32(const void* p) {
    uint32_t a;
    asm("{ .reg .u64 t; cvta.to.shared.u64 t, %1; cvt.u32.u64 %0, t; }"
        : "=r"(a) : "l"(p));
    return a;
}

#define CP_ASYNC16(dst, src) \
    asm volatile("cp.async.cg.shared.global [%0], [%1], 16;" \
                 :: "r"(dst), "l"(src))
#define CP_COMMIT() asm volatile("cp.async.commit_group;" ::: "memory")
#define CP_WAIT(n)  asm volatile("cp.async.wait_group %0;" :: "n"(n) : "memory")

__device__ __forceinline__ void ldmx4(uint32_t* r, uint32_t addr) {
    asm volatile("ldmatrix.sync.aligned.m8n8.x4.shared.b16 {%0,%1,%2,%3}, [%4];"
                 : "=r"(r[0]), "=r"(r[1]), "=r"(r[2]), "=r"(r[3]) : "r"(addr));
}
__device__ __forceinline__ void ldmx4t(uint32_t* r, uint32_t addr) {
    asm volatile("ldmatrix.sync.aligned.m8n8.x4.trans.shared.b16 {%0,%1,%2,%3}, [%4];"
                 : "=r"(r[0]), "=r"(r[1]), "=r"(r[2]), "=r"(r[3]) : "r"(addr));
}
__device__ __forceinline__ void mma16816(float* d, const uint32_t* a,
                                         const uint32_t* b) {
    asm volatile(
        "mma.sync.aligned.m16n8k16.row.col.f32.bf16.bf16.f32 "
        "{%0,%1,%2,%3}, {%4,%5,%6,%7}, {%8,%9}, {%0,%1,%2,%3};"
        : "+f"(d[0]), "+f"(d[1]), "+f"(d[2]), "+f"(d[3])
        : "r"(a[0]), "r"(a[1]), "r"(a[2]), "r"(a[3]), "r"(b[0]), "r"(b[1]));
}

__device__ __forceinline__ void psplit(float a, float b,
                                       uint32_t& hi, uint32_t& lo) {
    __nv_bfloat16 ha = __float2bfloat16(a), hb = __float2bfloat16(b);
    __nv_bfloat16 la = __float2bfloat16(a - __bfloat162float(ha));
    __nv_bfloat16 lb = __float2bfloat16(b - __bfloat162float(hb));
    __nv_bfloat162 h2 = __halves2bfloat162(ha, hb);
    __nv_bfloat162 l2 = __halves2bfloat162(la, lb);
    hi = *reinterpret_cast<uint32_t*>(&h2);
    lo = *reinterpret_cast<uint32_t*>(&l2);
}

__device__ __forceinline__ void wsplit(__nv_bfloat16* hi, __nv_bfloat16* lo,
                                       size_t o, float a, float b) {
    __nv_bfloat16 ha = __float2bfloat16(a), hb = __float2bfloat16(b);
    __nv_bfloat16 la = __float2bfloat16(a - __bfloat162float(ha));
    __nv_bfloat16 lb = __float2bfloat16(b - __bfloat162float(hb));
    *reinterpret_cast<__nv_bfloat162*>(hi + o) = __halves2bfloat162(ha, hb);
    *reinterpret_cast<__nv_bfloat162*>(lo + o) = __halves2bfloat162(la, lb);
}

// ---------------------------------------------------------------------------
// Split-precision conversion kernels
// ---------------------------------------------------------------------------
__global__ __launch_bounds__(256) void convert_split(
    const float* __restrict__ in, __nv_bfloat16* __restrict__ hi,
    __nv_bfloat16* __restrict__ lo)
{
    int i = (blockIdx.x * blockDim.x + threadIdx.x) << 2;
    float4 v = *(const float4*)(in + i);
    wsplit(hi, lo, i, v.x, v.y);
    wsplit(hi, lo, i + 2, v.z, v.w);
}

// W[K][N] f32 -> Wt_hi/lo[N][K] bf16 (transpose + split)
__global__ __launch_bounds__(256) void transpose_split(
    const float* __restrict__ W, __nv_bfloat16* __restrict__ Thi,
    __nv_bfloat16* __restrict__ Tlo, int K, int N)
{
    __shared__ float t[32][33];
    int n0 = blockIdx.x << 5, k0 = blockIdx.y << 5;
    int tx = threadIdx.x, ty = threadIdx.y;   // 32 x 8
    #pragma unroll
    for (int i = 0; i < 4; i++)
        t[ty + 8 * i][tx] = W[(size_t)(k0 + ty + 8 * i) * N + n0 + tx];
    __syncthreads();
    #pragma unroll
    for (int i = 0; i < 4; i++) {
        float v = t[tx][ty + 8 * i];
        __nv_bfloat16 h = __float2bfloat16(v);
        __nv_bfloat16 l = __float2bfloat16(v - __bfloat162float(h));
        size_t o = (size_t)(n0 + ty + 8 * i) * K + k0 + tx;
        Thi[o] = h;
        Tlo[o] = l;
    }
}

// ---------------------------------------------------------------------------
// Split-bf16 GEMM via mma.sync. 128x128 CTA, 8 warps (2x4) of 64x32 tiles.
// Sequential 3-mma-per-accumulator ordering (round-6, measured fastest).
// QKV variant fuses bias+RoPE+scatter+split.
// ---------------------------------------------------------------------------
#define TILE_B 10240
#define STAGE_B 40960

__device__ __forceinline__ void gemm_load_chunk(
    uint32_t sst,
    const __nv_bfloat16* __restrict__ Ahi, const __nv_bfloat16* __restrict__ Alo,
    const __nv_bfloat16* __restrict__ Bhi, const __nv_bfloat16* __restrict__ Blo,
    int bm, int bn, int K, int k0, int tid)
{
    #pragma unroll
    for (int j = 0; j < 2; j++) {
        int u = tid + (j << 8);
        int r = u >> 2;
        int c16 = (u & 3) << 4;
        uint32_t d = sst + (uint32_t)r * 80 + c16;
        size_t ga = ((size_t)(bm + r) * K + k0) * 2 + c16;
        size_t gb = ((size_t)(bn + r) * K + k0) * 2 + c16;
        CP_ASYNC16(d,               (const char*)Ahi + ga);
        CP_ASYNC16(d + TILE_B,      (const char*)Alo + ga);
        CP_ASYNC16(d + 2 * TILE_B,  (const char*)Bhi + gb);
        CP_ASYNC16(d + 3 * TILE_B,  (const char*)Blo + gb);
    }
}

template<bool QKV>
__global__ __launch_bounds__(256) void gemm_mma(
    const __nv_bfloat16* __restrict__ Ahi, const __nv_bfloat16* __restrict__ Alo,
    const __nv_bfloat16* __restrict__ Bhi, const __nv_bfloat16* __restrict__ Blo,
    const float* __restrict__ bias, float* __restrict__ C,
    int M, int N, int K,
    const float* __restrict__ cs, const float* __restrict__ sn,
    float* __restrict__ out_k, float* __restrict__ out_v,
    __nv_bfloat16* __restrict__ qhx, __nv_bfloat16* __restrict__ qlx,
    __nv_bfloat16* __restrict__ khx, __nv_bfloat16* __restrict__ klx,
    __nv_bfloat16* __restrict__ vhx, __nv_bfloat16* __restrict__ vlx)
{
    extern __shared__ char smem[];
    const uint32_t sb = smem_u32(smem);

    const int tid = threadIdx.x;
    const int wid = tid >> 5;
    const int lane = tid & 31;
    const int bm = blockIdx.y << 7, bn = blockIdx.x << 7;
    const int wm = (wid >> 2) << 6;          // 0 or 64
    const int wn = (wid & 3) << 5;           // 0,32,64,96

    float acc[4][4][4] = {};                 // [m16][n8][frag]

    gemm_load_chunk(sb, Ahi, Alo, Bhi, Blo, bm, bn, K, 0, tid);
    CP_COMMIT();

    const int nchunk = K >> 5;
    for (int c = 0; c < nchunk; c++) {
        const uint32_t st = sb + (uint32_t)(c & 1) * STAGE_B;
        if (c + 1 < nchunk) {
            gemm_load_chunk(sb + (uint32_t)((c + 1) & 1) * STAGE_B,
                            Ahi, Alo, Bhi, Blo, bm, bn, K, (c + 1) << 5, tid);
            CP_COMMIT();
            CP_WAIT(1);
        } else {
            CP_WAIT(0);
        }
        __syncthreads();

        #pragma unroll
        for (int ks = 0; ks < 2; ks++) {
            const int kb = ks << 5;
            uint32_t af[2][4][4];
            #pragma unroll
            for (int s = 0; s < 2; s++) {
                uint32_t abase = st + (uint32_t)s * TILE_B;
                #pragma unroll
                for (int mt = 0; mt < 4; mt++) {
                    uint32_t addr = abase
                        + (uint32_t)(wm + (mt << 4) + (lane & 15)) * 80
                        + kb + ((lane >> 4) << 4);
                    ldmx4(af[s][mt], addr);
                }
            }
            uint32_t bf[2][8];
            #pragma unroll
            for (int s = 0; s < 2; s++) {
                uint32_t bbase = st + (uint32_t)(2 + s) * TILE_B;
                #pragma unroll
                for (int g = 0; g < 2; g++) {
                    uint32_t nrow = wn + (g << 4) + (((lane >> 4) & 1) << 3)
                                  + (lane & 7);
                    uint32_t addr = bbase + nrow * 80 + kb
                                  + (((lane >> 3) & 1) << 4);
                    ldmx4(&bf[s][g << 2], addr);
                }
            }
            // sequential 3-pass per accumulator (round-6 ordering)
            #pragma unroll
            for (int mt = 0; mt < 4; mt++)
                #pragma unroll
                for (int nt = 0; nt < 4; nt++) {
                    mma16816(acc[mt][nt], af[0][mt], &bf[0][nt << 1]);
                    mma16816(acc[mt][nt], af[0][mt], &bf[1][nt << 1]);
                    mma16816(acc[mt][nt], af[1][mt], &bf[0][nt << 1]);
                }
        }
        __syncthreads();
    }

    const int r0 = bm + wm + (lane >> 2);
    const int cc0 = bn + wn + ((lane & 3) << 1);

    if (!QKV) {
        #pragma unroll
        for (int mt = 0; mt < 4; mt++) {
            #pragma unroll
            for (int nt = 0; nt < 4; nt++) {
                int col = cc0 + (nt << 3);
                float b0 = bias[col], b1 = bias[col + 1];
                int ra = r0 + (mt << 4);
                float2 v0 = make_float2(acc[mt][nt][0] + b0, acc[mt][nt][1] + b1);
                float2 v1 = make_float2(acc[mt][nt][2] + b0, acc[mt][nt][3] + b1);
                *(float2*)&C[(size_t)ra * N + col] = v0;
                *(float2*)&C[(size_t)(ra + 8) * N + col] = v1;
            }
        }
    } else {
        // fused bias + RoPE + head scatter + hi/lo split
        const int region = bn >> 10;            // 0=q, 1=k, 2=v
        #pragma unroll
        for (int mt = 0; mt < 4; mt++) {
            #pragma unroll
            for (int rr = 0; rr < 2; rr++) {
                int row = r0 + (mt << 4) + (rr << 3);
                int s = row & 2047, bb = row >> 11;
                #pragma unroll
                for (int nt = 0; nt < 4; nt++) {
                    int col = cc0 + (nt << 3);
                    float2 bp = *(const float2*)&bias[col];
                    float v0 = acc[mt][nt][rr * 2]     + bp.x;
                    float v1 = acc[mt][nt][rr * 2 + 1] + bp.y;
                    int d = col - (region << 10);
                    int h = d >> 6, hd = d & 63;
                    size_t o = (((size_t)(bb * 16 + h)) * 2048 + s) * 64 + hd;
                    if (region == 2) {
                        wsplit(vhx, vlx, o, v0, v1);
                        *(float2*)&out_v[o] = make_float2(v0, v1);
                    } else {
                        float2 cp = *(const float2*)&cs[s * 64 + hd];
                        float2 sp = *(const float2*)&sn[s * 64 + hd];
                        float rv0 = v0 * cp.x - v1 * sp.x;
                        float rv1 = v1 * cp.y + v0 * sp.y;
                        if (region == 0) {
                            wsplit(qhx, qlx, o, rv0 * 0.125f, rv1 * 0.125f);
                        } else {
                            wsplit(khx, klx, o, rv0, rv1);
                            *(float2*)&out_k[o] = make_float2(rv0, rv1);
                        }
                    }
                }
            }
        }
    }
}

// ---------------------------------------------------------------------------
// Flash attention via mma.sync, sequential 3-mma ordering.
// CTA = 128 q-rows of one (b,h); 8 warps x 16 rows; 32 kv tiles of 64.
// ---------------------------------------------------------------------------
#define AST 144
#define ASTG 36864

__global__ __launch_bounds__(256) void attn_mma(
    const __nv_bfloat16* __restrict__ qhi, const __nv_bfloat16* __restrict__ qlo,
    const __nv_bfloat16* __restrict__ khi, const __nv_bfloat16* __restrict__ klo,
    const __nv_bfloat16* __restrict__ vhi, const __nv_bfloat16* __restrict__ vlo,
    __nv_bfloat16* __restrict__ yhi, __nv_bfloat16* __restrict__ ylo)
{
    extern __shared__ char smx[];
    const uint32_t sb = smem_u32(smx);
    const int tid = threadIdx.x, wid = tid >> 5, lane = tid & 31;
    const int bh = blockIdx.y, q0 = blockIdx.x << 7;
    const uint32_t QH = sb + ASTG, QL = QH + 18432;

    const size_t hbase = (size_t)bh * 2048 * 64;
    const char* kh = (const char*)(khi + hbase);
    const char* kl = (const char*)(klo + hbase);
    const char* vh = (const char*)(vhi + hbase);
    const char* vl = (const char*)(vlo + hbase);

    {
        const char* qhg = (const char*)(qhi + hbase + (size_t)q0 * 64);
        const char* qlg = (const char*)(qlo + hbase + (size_t)q0 * 64);
        #pragma unroll
        for (int j = 0; j < 4; j++) {
            int u = tid + (j << 8); int r = u >> 3; int c = (u & 7) << 4;
            CP_ASYNC16(QH + r * AST + c, qhg + r * 128 + c);
            CP_ASYNC16(QL + r * AST + c, qlg + r * 128 + c);
        }
        CP_COMMIT();
    }
    {
        #pragma unroll
        for (int j = 0; j < 2; j++) {
            int u = tid + (j << 8); int r = u >> 3; int c = (u & 7) << 4;
            uint32_t d = sb + r * AST + c;
            int go = r * 128 + c;
            CP_ASYNC16(d, kh + go);         CP_ASYNC16(d + 9216, kl + go);
            CP_ASYNC16(d + 18432, vh + go); CP_ASYNC16(d + 27648, vl + go);
        }
        CP_COMMIT();
    }
    CP_WAIT(1);
    __syncthreads();

    uint32_t qfh[4][4], qfl[4][4];
    #pragma unroll
    for (int kt = 0; kt < 4; kt++) {
        uint32_t a = QH + (uint32_t)((wid << 4) + (lane & 15)) * AST
                   + (kt << 5) + ((lane >> 4) << 4);
        ldmx4(qfh[kt], a);
        ldmx4(qfl[kt], a + 18432);
    }
    __syncthreads();

    float m0 = -1e30f, m1 = -1e30f, l0 = 0.f, l1 = 0.f;
    float o[8][4] = {};

    for (int t = 0; t < 32; t++) {
        const uint32_t st = sb + (uint32_t)(t & 1) * ASTG;
        if (t + 1 < 32) {
            uint32_t dstg = sb + (uint32_t)((t + 1) & 1) * ASTG;
            size_t tb = (size_t)(t + 1) * 64 * 128;
            #pragma unroll
            for (int j = 0; j < 2; j++) {
                int u = tid + (j << 8); int r = u >> 3; int c = (u & 7) << 4;
                uint32_t d = dstg + r * AST + c;
                size_t go = tb + r * 128 + c;
                CP_ASYNC16(d, kh + go);         CP_ASYNC16(d + 9216, kl + go);
                CP_ASYNC16(d + 18432, vh + go); CP_ASYNC16(d + 27648, vl + go);
            }
            CP_COMMIT();
            CP_WAIT(1);
        } else {
            CP_WAIT(0);
        }
        __syncthreads();

        // S = Q K^T, sequential 3-pass per accumulator
        float sacc[8][4] = {};
        #pragma unroll
        for (int kt = 0; kt < 4; kt++) {
            #pragma unroll
            for (int g = 0; g < 4; g++) {
                uint32_t na = st
                    + (uint32_t)((g << 4) + (((lane >> 4) & 1) << 3) + (lane & 7)) * AST
                    + (kt << 5) + (((lane >> 3) & 1) << 4);
                uint32_t kfh[4], kfl[4];
                ldmx4(kfh, na);
                ldmx4(kfl, na + 9216);
                mma16816(sacc[2 * g],     qfh[kt], &kfh[0]);
                mma16816(sacc[2 * g],     qfh[kt], &kfl[0]);
                mma16816(sacc[2 * g],     qfl[kt], &kfh[0]);
                mma16816(sacc[2 * g + 1], qfh[kt], &kfh[2]);
                mma16816(sacc[2 * g + 1], qfh[kt], &kfl[2]);
                mma16816(sacc[2 * g + 1], qfl[kt], &kfh[2]);
            }
        }

        float mx0 = -1e30f, mx1 = -1e30f;
        #pragma unroll
        for (int n = 0; n < 8; n++) {
            mx0 = fmaxf(mx0, fmaxf(sacc[n][0], sacc[n][1]));
            mx1 = fmaxf(mx1, fmaxf(sacc[n][2], sacc[n][3]));
        }
        mx0 = fmaxf(mx0, __shfl_xor_sync(0xffffffffu, mx0, 1));
        mx0 = fmaxf(mx0, __shfl_xor_sync(0xffffffffu, mx0, 2));
        mx1 = fmaxf(mx1, __shfl_xor_sync(0xffffffffu, mx1, 1));
        mx1 = fmaxf(mx1, __shfl_xor_sync(0xffffffffu, mx1, 2));
        float nm0 = fmaxf(m0, mx0), nm1 = fmaxf(m1, mx1);
        float al0 = __expf(m0 - nm0), al1 = __expf(m1 - nm1);
        float rs0 = 0.f, rs1 = 0.f;
        #pragma unroll
        for (int n = 0; n < 8; n++) {
            sacc[n][0] = __expf(sacc[n][0] - nm0);
            sacc[n][1] = __expf(sacc[n][1] - nm0);
            sacc[n][2] = __expf(sacc[n][2] - nm1);
            sacc[n][3] = __expf(sacc[n][3] - nm1);
            rs0 += sacc[n][0] + sacc[n][1];
            rs1 += sacc[n][2] + sacc[n][3];
        }
        rs0 += __shfl_xor_sync(0xffffffffu, rs0, 1);
        rs0 += __shfl_xor_sync(0xffffffffu, rs0, 2);
        rs1 += __shfl_xor_sync(0xffffffffu, rs1, 1);
        rs1 += __shfl_xor_sync(0xffffffffu, rs1, 2);
        l0 = l0 * al0 + rs0; l1 = l1 * al1 + rs1;
        m0 = nm0; m1 = nm1;
        #pragma unroll
        for (int n = 0; n < 8; n++) {
            o[n][0] *= al0; o[n][1] *= al0;
            o[n][2] *= al1; o[n][3] *= al1;
        }

        // O += P V, sequential 3-pass per accumulator
        #pragma unroll
        for (int kt = 0; kt < 4; kt++) {
            uint32_t ph[4], pl[4];
            psplit(sacc[2 * kt][0],     sacc[2 * kt][1],     ph[0], pl[0]);
            psplit(sacc[2 * kt][2],     sacc[2 * kt][3],     ph[1], pl[1]);
            psplit(sacc[2 * kt + 1][0], sacc[2 * kt + 1][1], ph[2], pl[2]);
            psplit(sacc[2 * kt + 1][2], sacc[2 * kt + 1][3], ph[3], pl[3]);
            #pragma unroll
            for (int g = 0; g < 4; g++) {
                uint32_t va = st + 18432
                    + (uint32_t)((kt << 4) + (lane & 7) + (((lane >> 3) & 1) << 3)) * AST
                    + (((g << 4) + (((lane >> 4) & 1) << 3)) << 1);
                uint32_t vfh[4], vfl[4];
                ldmx4t(vfh, va);
                ldmx4t(vfl, va + 9216);
                mma16816(o[2 * g],     ph, &vfh[0]);
                mma16816(o[2 * g],     ph, &vfl[0]);
                mma16816(o[2 * g],     pl, &vfh[0]);
                mma16816(o[2 * g + 1], ph, &vfh[2]);
                mma16816(o[2 * g + 1], ph, &vfl[2]);
                mma16816(o[2 * g + 1], pl, &vfh[2]);
            }
        }
        __syncthreads();
    }

    float il0 = 1.f / l0, il1 = 1.f / l1;
    const int b = bh >> 4, h = bh & 15;
    const int r0 = b * 2048 + q0 + (wid << 4) + (lane >> 2);
    const int c0 = h * 64 + ((lane & 3) << 1);
    #pragma unroll
    for (int n = 0; n < 8; n++) {
        size_t o0 = (size_t)r0 * 1024 + c0 + (n << 3);
        wsplit(yhi, ylo, o0, o[n][0] * il0, o[n][1] * il0);
        wsplit(yhi, ylo, o0 + 8 * 1024, o[n][2] * il1, o[n][3] * il1);
    }
}

// ---------------------------------------------------------------------------
extern "C" void kernel_launch(void* const* d_in, const int* in_sizes, int n_in,
                              void* d_out, int out_size)
{
    const float* x     = (const float*)d_in[0];
    const float* cs    = (const float*)d_in[1];
    const float* sn    = (const float*)d_in[2];
    const float* Wqkv  = (const float*)d_in[3];
    const float* bqkv  = (const float*)d_in[4];
    const float* Wproj = (const float*)d_in[5];
    const float* bproj = (const float*)d_in[6];

    float* out   = (float*)d_out;
    float* out_y = out;
    float* out_k = out + (size_t)2 * 2048 * 1024;
    float* out_v = out_k + (size_t)2 * 16 * 2048 * 64;

    __nv_bfloat16 *xhi, *xlo, *wqh, *wql, *wph, *wpl, *yhi, *ylo;
    __nv_bfloat16 *qh, *ql, *kh, *kl, *vh, *vl;
    cudaGetSymbolAddress((void**)&xhi, g_xhi);
    cudaGetSymbolAddress((void**)&xlo, g_xlo);
    cudaGetSymbolAddress((void**)&wqh, g_wqt_hi);
    cudaGetSymbolAddress((void**)&wql, g_wqt_lo);
    cudaGetSymbolAddress((void**)&wph, g_wpt_hi);
    cudaGetSymbolAddress((void**)&wpl, g_wpt_lo);
    cudaGetSymbolAddress((void**)&yhi, g_yhi);
    cudaGetSymbolAddress((void**)&ylo, g_ylo);
    cudaGetSymbolAddress((void**)&qh, g_qh);
    cudaGetSymbolAddress((void**)&ql, g_ql);
    cudaGetSymbolAddress((void**)&kh, g_kh);
    cudaGetSymbolAddress((void**)&kl, g_kl);
    cudaGetSymbolAddress((void**)&vh, g_vh);
    cudaGetSymbolAddress((void**)&vl, g_vl);

    const int gemm_smem = 2 * STAGE_B;
    cudaFuncSetAttribute(gemm_mma<true>,
                         cudaFuncAttributeMaxDynamicSharedMemorySize, gemm_smem);
    cudaFuncSetAttribute(gemm_mma<false>,
                         cudaFuncAttributeMaxDynamicSharedMemorySize, gemm_smem);
    const int attn_smem = 2 * ASTG;
    cudaFuncSetAttribute(attn_mma,
                         cudaFuncAttributeMaxDynamicSharedMemorySize, attn_smem);

    // 0) split conversions
    convert_split<<<4096, 256>>>(x, xhi, xlo);
    transpose_split<<<dim3(96, 32), dim3(32, 8)>>>(Wqkv, wqh, wql, 1024, 3072);
    transpose_split<<<dim3(32, 32), dim3(32, 8)>>>(Wproj, wph, wpl, 1024, 1024);

    // 1) QKV GEMM + fused bias/RoPE/scatter/split
    gemm_mma<true><<<dim3(24, 32), 256, gemm_smem>>>(
        xhi, xlo, wqh, wql, bqkv, nullptr, 4096, 3072, 1024,
        cs, sn, out_k, out_v, qh, ql, kh, kl, vh, vl);

    // 2) Attention -> y splits
    attn_mma<<<dim3(16, 32), 256, attn_smem>>>(
        qh, ql, kh, kl, vh, vl, yhi, ylo);

    // 3) Projection
    gemm_mma<false><<<dim3(8, 32), 256, gemm_smem>>>(
        yhi, ylo, wph, wpl, bproj, out_y, 4096, 1024, 1024,
        nullptr, nullptr, nullptr, nullptr,
        nullptr, nullptr, nullptr, nullptr, nullptr, nullptr);
}

// round 10
// speedup vs baseline: 1.0921x; 1.0862x over previous
#include <cuda_runtime.h>
#include <cuda_bf16.h>
#include <math.h>
#include <stdint.h>

// B=2, S=2048, D=1024, H=16, HD=64

// ---------------- scratch (device globals) ----------------
__device__ __nv_bfloat16 g_xhi[4194304], g_xlo[4194304];       // x split
__device__ __nv_bfloat16 g_wqt_hi[3145728], g_wqt_lo[3145728]; // Wqkv^T split
__device__ __nv_bfloat16 g_wpt_hi[1048576], g_wpt_lo[1048576]; // Wproj^T split
__device__ __nv_bfloat16 g_yhi[4194304], g_ylo[4194304];       // attn out split

__device__ __nv_bfloat16 g_qh[4194304], g_ql[4194304];         // q heads split
__device__ __nv_bfloat16 g_kh[4194304], g_kl[4194304];         // k heads split
__device__ __nv_bfloat16 g_vh[4194304], g_vl[4194304];         // v heads split

// ---------------- helpers ----------------
__device__ __forceinline__ uint32_t smem_u32(const void* p) {
    uint32_t a;
    asm("{ .reg .u64 t; cvta.to.shared.u64 t, %1; cvt.u32.u64 %0, t; }"
        : "=r"(a) : "l"(p));
    return a;
}

#define CP_ASYNC16(dst, src) \
    asm volatile("cp.async.cg.shared.global [%0], [%1], 16;" \
                 :: "r"(dst), "l"(src))
#define CP_COMMIT() asm volatile("cp.async.commit_group;" ::: "memory")
#define CP_WAIT(n)  asm volatile("cp.async.wait_group %0;" :: "n"(n) : "memory")

__device__ __forceinline__ void ldmx4(uint32_t* r, uint32_t addr) {
    asm volatile("ldmatrix.sync.aligned.m8n8.x4.shared.b16 {%0,%1,%2,%3}, [%4];"
                 : "=r"(r[0]), "=r"(r[1]), "=r"(r[2]), "=r"(r[3]) : "r"(addr));
}
__device__ __forceinline__ void ldmx4t(uint32_t* r, uint32_t addr) {
    asm volatile("ldmatrix.sync.aligned.m8n8.x4.trans.shared.b16 {%0,%1,%2,%3}, [%4];"
                 : "=r"(r[0]), "=r"(r[1]), "=r"(r[2]), "=r"(r[3]) : "r"(addr));
}
__device__ __forceinline__ void mma16816(float* d, const uint32_t* a,
                                         const uint32_t* b) {
    asm volatile(
        "mma.sync.aligned.m16n8k16.row.col.f32.bf16.bf16.f32 "
        "{%0,%1,%2,%3}, {%4,%5,%6,%7}, {%8,%9}, {%0,%1,%2,%3};"
        : "+f"(d[0]), "+f"(d[1]), "+f"(d[2]), "+f"(d[3])
        : "r"(a[0]), "r"(a[1]), "r"(a[2]), "r"(a[3]), "r"(b[0]), "r"(b[1]));
}

__device__ __forceinline__ void psplit(float a, float b,
                                       uint32_t& hi, uint32_t& lo) {
    __nv_bfloat16 ha = __float2bfloat16(a), hb = __float2bfloat16(b);
    __nv_bfloat16 la = __float2bfloat16(a - __bfloat162float(ha));
    __nv_bfloat16 lb = __float2bfloat16(b - __bfloat162float(hb));
    __nv_bfloat162 h2 = __halves2bfloat162(ha, hb);
    __nv_bfloat162 l2 = __halves2bfloat162(la, lb);
    hi = *reinterpret_cast<uint32_t*>(&h2);
    lo = *reinterpret_cast<uint32_t*>(&l2);
}

__device__ __forceinline__ void wsplit(__nv_bfloat16* hi, __nv_bfloat16* lo,
                                       size_t o, float a, float b) {
    __nv_bfloat16 ha = __float2bfloat16(a), hb = __float2bfloat16(b);
    __nv_bfloat16 la = __float2bfloat16(a - __bfloat162float(ha));
    __nv_bfloat16 lb = __float2bfloat16(b - __bfloat162float(hb));
    *reinterpret_cast<__nv_bfloat162*>(hi + o) = __halves2bfloat162(ha, hb);
    *reinterpret_cast<__nv_bfloat162*>(lo + o) = __halves2bfloat162(la, lb);
}

// ---------------------------------------------------------------------------
// Split-precision conversion kernels
// ---------------------------------------------------------------------------
__global__ __launch_bounds__(256) void convert_split(
    const float* __restrict__ in, __nv_bfloat16* __restrict__ hi,
    __nv_bfloat16* __restrict__ lo)
{
    int i = (blockIdx.x * blockDim.x + threadIdx.x) << 2;
    float4 v = *(const float4*)(in + i);
    wsplit(hi, lo, i, v.x, v.y);
    wsplit(hi, lo, i + 2, v.z, v.w);
}

// Both weights transpose+split in one launch.
// blockIdx.x < 96: Wqkv (N=3072); else Wproj (N=1024). K=1024 both.
__global__ __launch_bounds__(256) void transpose_split2(
    const float* __restrict__ Wq, const float* __restrict__ Wp,
    __nv_bfloat16* __restrict__ qThi, __nv_bfloat16* __restrict__ qTlo,
    __nv_bfloat16* __restrict__ pThi, __nv_bfloat16* __restrict__ pTlo)
{
    __shared__ float t[32][33];
    const int K = 1024;
    int bx = blockIdx.x;
    const float* W;
    __nv_bfloat16 *Thi, *Tlo;
    int N;
    if (bx < 96) { W = Wq; Thi = qThi; Tlo = qTlo; N = 3072; }
    else         { W = Wp; Thi = pThi; Tlo = pTlo; N = 1024; bx -= 96; }

    int n0 = bx << 5, k0 = blockIdx.y << 5;
    int tx = threadIdx.x, ty = threadIdx.y;   // 32 x 8
    #pragma unroll
    for (int i = 0; i < 4; i++)
        t[ty + 8 * i][tx] = W[(size_t)(k0 + ty + 8 * i) * N + n0 + tx];
    __syncthreads();
    #pragma unroll
    for (int i = 0; i < 4; i++) {
        float v = t[tx][ty + 8 * i];
        __nv_bfloat16 h = __float2bfloat16(v);
        __nv_bfloat16 l = __float2bfloat16(v - __bfloat162float(h));
        size_t o = (size_t)(n0 + ty + 8 * i) * K + k0 + tx;
        Thi[o] = h;
        Tlo[o] = l;
    }
}

// ---------------------------------------------------------------------------
// Split-bf16 GEMM via mma.sync. 128x128 CTA, 8 warps (2x4) of 64x32 tiles.
// QKV variant fuses bias+RoPE+scatter+split. (Round-9 form, unchanged.)
// ---------------------------------------------------------------------------
#define TILE_B 10240
#define STAGE_B 40960

__device__ __forceinline__ void gemm_load_chunk(
    uint32_t sst,
    const __nv_bfloat16* __restrict__ Ahi, const __nv_bfloat16* __restrict__ Alo,
    const __nv_bfloat16* __restrict__ Bhi, const __nv_bfloat16* __restrict__ Blo,
    int bm, int bn, int K, int k0, int tid)
{
    #pragma unroll
    for (int j = 0; j < 2; j++) {
        int u = tid + (j << 8);
        int r = u >> 2;
        int c16 = (u & 3) << 4;
        uint32_t d = sst + (uint32_t)r * 80 + c16;
        size_t ga = ((size_t)(bm + r) * K + k0) * 2 + c16;
        size_t gb = ((size_t)(bn + r) * K + k0) * 2 + c16;
        CP_ASYNC16(d,               (const char*)Ahi + ga);
        CP_ASYNC16(d + TILE_B,      (const char*)Alo + ga);
        CP_ASYNC16(d + 2 * TILE_B,  (const char*)Bhi + gb);
        CP_ASYNC16(d + 3 * TILE_B,  (const char*)Blo + gb);
    }
}

template<bool QKV>
__global__ __launch_bounds__(256) void gemm_mma(
    const __nv_bfloat16* __restrict__ Ahi, const __nv_bfloat16* __restrict__ Alo,
    const __nv_bfloat16* __restrict__ Bhi, const __nv_bfloat16* __restrict__ Blo,
    const float* __restrict__ bias, float* __restrict__ C,
    int M, int N, int K,
    const float* __restrict__ cs, const float* __restrict__ sn,
    float* __restrict__ out_k, float* __restrict__ out_v,
    __nv_bfloat16* __restrict__ qhx, __nv_bfloat16* __restrict__ qlx,
    __nv_bfloat16* __restrict__ khx, __nv_bfloat16* __restrict__ klx,
    __nv_bfloat16* __restrict__ vhx, __nv_bfloat16* __restrict__ vlx)
{
    extern __shared__ char smem[];
    const uint32_t sb = smem_u32(smem);

    const int tid = threadIdx.x;
    const int wid = tid >> 5;
    const int lane = tid & 31;
    const int bm = blockIdx.y << 7, bn = blockIdx.x << 7;
    const int wm = (wid >> 2) << 6;
    const int wn = (wid & 3) << 5;

    float acc[4][4][4] = {};

    gemm_load_chunk(sb, Ahi, Alo, Bhi, Blo, bm, bn, K, 0, tid);
    CP_COMMIT();

    const int nchunk = K >> 5;
    for (int c = 0; c < nchunk; c++) {
        const uint32_t st = sb + (uint32_t)(c & 1) * STAGE_B;
        if (c + 1 < nchunk) {
            gemm_load_chunk(sb + (uint32_t)((c + 1) & 1) * STAGE_B,
                            Ahi, Alo, Bhi, Blo, bm, bn, K, (c + 1) << 5, tid);
            CP_COMMIT();
            CP_WAIT(1);
        } else {
            CP_WAIT(0);
        }
        __syncthreads();

        #pragma unroll
        for (int ks = 0; ks < 2; ks++) {
            const int kb = ks << 5;
            uint32_t af[2][4][4];
            #pragma unroll
            for (int s = 0; s < 2; s++) {
                uint32_t abase = st + (uint32_t)s * TILE_B;
                #pragma unroll
                for (int mt = 0; mt < 4; mt++) {
                    uint32_t addr = abase
                        + (uint32_t)(wm + (mt << 4) + (lane & 15)) * 80
                        + kb + ((lane >> 4) << 4);
                    ldmx4(af[s][mt], addr);
                }
            }
            uint32_t bf[2][8];
            #pragma unroll
            for (int s = 0; s < 2; s++) {
                uint32_t bbase = st + (uint32_t)(2 + s) * TILE_B;
                #pragma unroll
                for (int g = 0; g < 2; g++) {
                    uint32_t nrow = wn + (g << 4) + (((lane >> 4) & 1) << 3)
                                  + (lane & 7);
                    uint32_t addr = bbase + nrow * 80 + kb
                                  + (((lane >> 3) & 1) << 4);
                    ldmx4(&bf[s][g << 2], addr);
                }
            }
            #pragma unroll
            for (int mt = 0; mt < 4; mt++)
                #pragma unroll
                for (int nt = 0; nt < 4; nt++) {
                    mma16816(acc[mt][nt], af[0][mt], &bf[0][nt << 1]);
                    mma16816(acc[mt][nt], af[0][mt], &bf[1][nt << 1]);
                    mma16816(acc[mt][nt], af[1][mt], &bf[0][nt << 1]);
                }
        }
        __syncthreads();
    }

    const int r0 = bm + wm + (lane >> 2);
    const int cc0 = bn + wn + ((lane & 3) << 1);

    if (!QKV) {
        #pragma unroll
        for (int mt = 0; mt < 4; mt++) {
            #pragma unroll
            for (int nt = 0; nt < 4; nt++) {
                int col = cc0 + (nt << 3);
                float b0 = bias[col], b1 = bias[col + 1];
                int ra = r0 + (mt << 4);
                float2 v0 = make_float2(acc[mt][nt][0] + b0, acc[mt][nt][1] + b1);
                float2 v1 = make_float2(acc[mt][nt][2] + b0, acc[mt][nt][3] + b1);
                *(float2*)&C[(size_t)ra * N + col] = v0;
                *(float2*)&C[(size_t)(ra + 8) * N + col] = v1;
            }
        }
    } else {
        const int region = bn >> 10;            // 0=q, 1=k, 2=v
        #pragma unroll
        for (int mt = 0; mt < 4; mt++) {
            #pragma unroll
            for (int rr = 0; rr < 2; rr++) {
                int row = r0 + (mt << 4) + (rr << 3);
                int s = row & 2047, bb = row >> 11;
                #pragma unroll
                for (int nt = 0; nt < 4; nt++) {
                    int col = cc0 + (nt << 3);
                    float2 bp = *(const float2*)&bias[col];
                    float v0 = acc[mt][nt][rr * 2]     + bp.x;
                    float v1 = acc[mt][nt][rr * 2 + 1] + bp.y;
                    int d = col - (region << 10);
                    int h = d >> 6, hd = d & 63;
                    size_t o = (((size_t)(bb * 16 + h)) * 2048 + s) * 64 + hd;
                    if (region == 2) {
                        wsplit(vhx, vlx, o, v0, v1);
                        *(float2*)&out_v[o] = make_float2(v0, v1);
                    } else {
                        float2 cp = *(const float2*)&cs[s * 64 + hd];
                        float2 sp = *(const float2*)&sn[s * 64 + hd];
                        float rv0 = v0 * cp.x - v1 * sp.x;
                        float rv1 = v1 * cp.y + v0 * sp.y;
                        if (region == 0) {
                            wsplit(qhx, qlx, o, rv0 * 0.125f, rv1 * 0.125f);
                        } else {
                            wsplit(khx, klx, o, rv0, rv1);
                            *(float2*)&out_k[o] = make_float2(rv0, rv1);
                        }
                    }
                }
            }
        }
    }
}

// ---------------------------------------------------------------------------
// Flash attention via mma.sync. NOW: 128 threads, 4 warps, 64 q-rows/CTA.
// regs/CTA halve -> 3 CTAs/SM (smem-capped), independent barrier groups.
// ---------------------------------------------------------------------------
#define AST 144
#define ASTG 36864

__global__ __launch_bounds__(128, 3) void attn_mma(
    const __nv_bfloat16* __restrict__ qhi, const __nv_bfloat16* __restrict__ qlo,
    const __nv_bfloat16* __restrict__ khi, const __nv_bfloat16* __restrict__ klo,
    const __nv_bfloat16* __restrict__ vhi, const __nv_bfloat16* __restrict__ vlo,
    __nv_bfloat16* __restrict__ yhi, __nv_bfloat16* __restrict__ ylo)
{
    extern __shared__ char smx[];
    const uint32_t sb = smem_u32(smx);
    const int tid = threadIdx.x, wid = tid >> 5, lane = tid & 31;
    const int bh = blockIdx.y, q0 = blockIdx.x << 6;     // 64 q-rows per CTA
    const uint32_t QH = sb + ASTG, QL = QH + 9216;       // Q staging (= stage 1)

    const size_t hbase = (size_t)bh * 2048 * 64;
    const char* kh = (const char*)(khi + hbase);
    const char* kl = (const char*)(klo + hbase);
    const char* vh = (const char*)(vhi + hbase);
    const char* vl = (const char*)(vlo + hbase);

    // Q -> smem (64 rows x 128B, hi+lo)
    {
        const char* qhg = (const char*)(qhi + hbase + (size_t)q0 * 64);
        const char* qlg = (const char*)(qlo + hbase + (size_t)q0 * 64);
        #pragma unroll
        for (int j = 0; j < 4; j++) {
            int u = tid + (j << 7); int r = u >> 3; int c = (u & 7) << 4;
            CP_ASYNC16(QH + r * AST + c, qhg + r * 128 + c);
            CP_ASYNC16(QL + r * AST + c, qlg + r * 128 + c);
        }
        CP_COMMIT();
    }
    // tile 0 -> stage 0
    {
        #pragma unroll
        for (int j = 0; j < 4; j++) {
            int u = tid + (j << 7); int r = u >> 3; int c = (u & 7) << 4;
            uint32_t d = sb + r * AST + c;
            int go = r * 128 + c;
            CP_ASYNC16(d, kh + go);         CP_ASYNC16(d + 9216, kl + go);
            CP_ASYNC16(d + 18432, vh + go); CP_ASYNC16(d + 27648, vl + go);
        }
        CP_COMMIT();
    }
    CP_WAIT(1);
    __syncthreads();

    // Q fragments (registers for whole kernel). Warp owns rows wid*16..+15.
    uint32_t qfh[4][4], qfl[4][4];
    #pragma unroll
    for (int kt = 0; kt < 4; kt++) {
        uint32_t a = QH + (uint32_t)((wid << 4) + (lane & 15)) * AST
                   + (kt << 5) + ((lane >> 4) << 4);
        ldmx4(qfh[kt], a);
        ldmx4(qfl[kt], a + 9216);
    }
    __syncthreads();   // Q region now reusable as stage 1

    float m0 = -1e30f, m1 = -1e30f, l0 = 0.f, l1 = 0.f;
    float o[8][4] = {};

    for (int t = 0; t < 32; t++) {
        const uint32_t st = sb + (uint32_t)(t & 1) * ASTG;
        if (t + 1 < 32) {
            uint32_t dstg = sb + (uint32_t)((t + 1) & 1) * ASTG;
            size_t tb = (size_t)(t + 1) * 64 * 128;
            #pragma unroll
            for (int j = 0; j < 4; j++) {
                int u = tid + (j << 7); int r = u >> 3; int c = (u & 7) << 4;
                uint32_t d = dstg + r * AST + c;
                size_t go = tb + r * 128 + c;
                CP_ASYNC16(d, kh + go);         CP_ASYNC16(d + 9216, kl + go);
                CP_ASYNC16(d + 18432, vh + go); CP_ASYNC16(d + 27648, vl + go);
            }
            CP_COMMIT();
            CP_WAIT(1);
        } else {
            CP_WAIT(0);
        }
        __syncthreads();

        // S = Q K^T (3-pass split)
        float sacc[8][4] = {};
        #pragma unroll
        for (int kt = 0; kt < 4; kt++) {
            #pragma unroll
            for (int g = 0; g < 4; g++) {
                uint32_t na = st
                    + (uint32_t)((g << 4) + (((lane >> 4) & 1) << 3) + (lane & 7)) * AST
                    + (kt << 5) + (((lane >> 3) & 1) << 4);
                uint32_t kfh[4], kfl[4];
                ldmx4(kfh, na);
                ldmx4(kfl, na + 9216);
                mma16816(sacc[2 * g],     qfh[kt], &kfh[0]);
                mma16816(sacc[2 * g],     qfh[kt], &kfl[0]);
                mma16816(sacc[2 * g],     qfl[kt], &kfh[0]);
                mma16816(sacc[2 * g + 1], qfh[kt], &kfh[2]);
                mma16816(sacc[2 * g + 1], qfh[kt], &kfl[2]);
                mma16816(sacc[2 * g + 1], qfl[kt], &kfh[2]);
            }
        }

        // online softmax
        float mx0 = -1e30f, mx1 = -1e30f;
        #pragma unroll
        for (int n = 0; n < 8; n++) {
            mx0 = fmaxf(mx0, fmaxf(sacc[n][0], sacc[n][1]));
            mx1 = fmaxf(mx1, fmaxf(sacc[n][2], sacc[n][3]));
        }
        mx0 = fmaxf(mx0, __shfl_xor_sync(0xffffffffu, mx0, 1));
        mx0 = fmaxf(mx0, __shfl_xor_sync(0xffffffffu, mx0, 2));
        mx1 = fmaxf(mx1, __shfl_xor_sync(0xffffffffu, mx1, 1));
        mx1 = fmaxf(mx1, __shfl_xor_sync(0xffffffffu, mx1, 2));
        float nm0 = fmaxf(m0, mx0), nm1 = fmaxf(m1, mx1);
        float al0 = __expf(m0 - nm0), al1 = __expf(m1 - nm1);
        float rs0 = 0.f, rs1 = 0.f;
        #pragma unroll
        for (int n = 0; n < 8; n++) {
            sacc[n][0] = __expf(sacc[n][0] - nm0);
            sacc[n][1] = __expf(sacc[n][1] - nm0);
            sacc[n][2] = __expf(sacc[n][2] - nm1);
            sacc[n][3] = __expf(sacc[n][3] - nm1);
            rs0 += sacc[n][0] + sacc[n][1];
            rs1 += sacc[n][2] + sacc[n][3];
        }
        rs0 += __shfl_xor_sync(0xffffffffu, rs0, 1);
        rs0 += __shfl_xor_sync(0xffffffffu, rs0, 2);
        rs1 += __shfl_xor_sync(0xffffffffu, rs1, 1);
        rs1 += __shfl_xor_sync(0xffffffffu, rs1, 2);
        l0 = l0 * al0 + rs0; l1 = l1 * al1 + rs1;
        m0 = nm0; m1 = nm1;
        #pragma unroll
        for (int n = 0; n < 8; n++) {
            o[n][0] *= al0; o[n][1] *= al0;
            o[n][2] *= al1; o[n][3] *= al1;
        }

        // O += P V (3-pass split)
        #pragma unroll
        for (int kt = 0; kt < 4; kt++) {
            uint32_t ph[4], pl[4];
            psplit(sacc[2 * kt][0],     sacc[2 * kt][1],     ph[0], pl[0]);
            psplit(sacc[2 * kt][2],     sacc[2 * kt][3],     ph[1], pl[1]);
            psplit(sacc[2 * kt + 1][0], sacc[2 * kt + 1][1], ph[2], pl[2]);
            psplit(sacc[2 * kt + 1][2], sacc[2 * kt + 1][3], ph[3], pl[3]);
            #pragma unroll
            for (int g = 0; g < 4; g++) {
                uint32_t va = st + 18432
                    + (uint32_t)((kt << 4) + (lane & 7) + (((lane >> 3) & 1) << 3)) * AST
                    + (((g << 4) + (((lane >> 4) & 1) << 3)) << 1);
                uint32_t vfh[4], vfl[4];
                ldmx4t(vfh, va);
                ldmx4t(vfl, va + 9216);
                mma16816(o[2 * g],     ph, &vfh[0]);
                mma16816(o[2 * g],     ph, &vfl[0]);
                mma16816(o[2 * g],     pl, &vfh[0]);
                mma16816(o[2 * g + 1], ph, &vfh[2]);
                mma16816(o[2 * g + 1], ph, &vfl[2]);
                mma16816(o[2 * g + 1], pl, &vfh[2]);
            }
        }
        __syncthreads();
    }

    // epilogue: y = O / l -> bf16 hi/lo splits (proj input)
    float il0 = 1.f / l0, il1 = 1.f / l1;
    const int b = bh >> 4, h = bh & 15;
    const int r0 = b * 2048 + q0 + (wid << 4) + (lane >> 2);
    const int c0 = h * 64 + ((lane & 3) << 1);
    #pragma unroll
    for (int n = 0; n < 8; n++) {
        size_t o0 = (size_t)r0 * 1024 + c0 + (n << 3);
        wsplit(yhi, ylo, o0, o[n][0] * il0, o[n][1] * il0);
        wsplit(yhi, ylo, o0 + 8 * 1024, o[n][2] * il1, o[n][3] * il1);
    }
}

// ---------------------------------------------------------------------------
extern "C" void kernel_launch(void* const* d_in, const int* in_sizes, int n_in,
                              void* d_out, int out_size)
{
    const float* x     = (const float*)d_in[0];
    const float* cs    = (const float*)d_in[1];
    const float* sn    = (const float*)d_in[2];
    const float* Wqkv  = (const float*)d_in[3];
    const float* bqkv  = (const float*)d_in[4];
    const float* Wproj = (const float*)d_in[5];
    const float* bproj = (const float*)d_in[6];

    float* out   = (float*)d_out;
    float* out_y = out;
    float* out_k = out + (size_t)2 * 2048 * 1024;
    float* out_v = out_k + (size_t)2 * 16 * 2048 * 64;

    __nv_bfloat16 *xhi, *xlo, *wqh, *wql, *wph, *wpl, *yhi, *ylo;
    __nv_bfloat16 *qh, *ql, *kh, *kl, *vh, *vl;
    cudaGetSymbolAddress((void**)&xhi, g_xhi);
    cudaGetSymbolAddress((void**)&xlo, g_xlo);
    cudaGetSymbolAddress((void**)&wqh, g_wqt_hi);
    cudaGetSymbolAddress((void**)&wql, g_wqt_lo);
    cudaGetSymbolAddress((void**)&wph, g_wpt_hi);
    cudaGetSymbolAddress((void**)&wpl, g_wpt_lo);
    cudaGetSymbolAddress((void**)&yhi, g_yhi);
    cudaGetSymbolAddress((void**)&ylo, g_ylo);
    cudaGetSymbolAddress((void**)&qh, g_qh);
    cudaGetSymbolAddress((void**)&ql, g_ql);
    cudaGetSymbolAddress((void**)&kh, g_kh);
    cudaGetSymbolAddress((void**)&kl, g_kl);
    cudaGetSymbolAddress((void**)&vh, g_vh);
    cudaGetSymbolAddress((void**)&vl, g_vl);

    const int gemm_smem = 2 * STAGE_B;
    cudaFuncSetAttribute(gemm_mma<true>,
                         cudaFuncAttributeMaxDynamicSharedMemorySize, gemm_smem);
    cudaFuncSetAttribute(gemm_mma<false>,
                         cudaFuncAttributeMaxDynamicSharedMemorySize, gemm_smem);
    const int attn_smem = 2 * ASTG;   // 73728
    cudaFuncSetAttribute(attn_mma,
                         cudaFuncAttributeMaxDynamicSharedMemorySize, attn_smem);

    // 0) split conversions
    convert_split<<<4096, 256>>>(x, xhi, xlo);
    transpose_split2<<<dim3(128, 32), dim3(32, 8)>>>(
        Wqkv, Wproj, wqh, wql, wph, wpl);

    // 1) QKV GEMM + fused bias/RoPE/scatter/split
    gemm_mma<true><<<dim3(24, 32), 256, gemm_smem>>>(
        xhi, xlo, wqh, wql, bqkv, nullptr, 4096, 3072, 1024,
        cs, sn, out_k, out_v, qh, ql, kh, kl, vh, vl);

    // 2) Attention -> y splits (128-thread CTAs, 3/SM)
    attn_mma<<<dim3(32, 32), 128, attn_smem>>>(
        qh, ql, kh, kl, vh, vl, yhi, ylo);

    // 3) Projection
    gemm_mma<false><<<dim3(8, 32), 256, gemm_smem>>>(
        yhi, ylo, wph, wpl, bproj, out_y, 4096, 1024, 1024,
        nullptr, nullptr, nullptr, nullptr,
        nullptr, nullptr, nullptr, nullptr, nullptr, nullptr);
}

// round 11
// speedup vs baseline: 2.3606x; 2.1616x over previous
#include <cuda_runtime.h>
#include <cuda_fp16.h>
#include <math.h>
#include <stdint.h>

// B=2, S=2048, D=1024, H=16, HD=64

// ---------------- scratch (device globals, fp16 single precision) ----------
__device__ __half g_xh[4194304];        // x fp16
__device__ __half g_wqt[3145728];       // Wqkv^T fp16
__device__ __half g_wpt[1048576];       // Wproj^T fp16
__device__ __half g_yh[4194304];        // attn out fp16
__device__ __half g_qh[4194304];        // q heads (rot+scaled) fp16
__device__ __half g_kh[4194304];        // k heads fp16
__device__ __half g_vh[4194304];        // v heads fp16

// ---------------- helpers ----------------
__device__ __forceinline__ uint32_t smem_u32(const void* p) {
    uint32_t a;
    asm("{ .reg .u64 t; cvta.to.shared.u64 t, %1; cvt.u32.u64 %0, t; }"
        : "=r"(a) : "l"(p));
    return a;
}

#define CP_ASYNC16(dst, src) \
    asm volatile("cp.async.cg.shared.global [%0], [%1], 16;" \
                 :: "r"(dst), "l"(src))
#define CP_COMMIT() asm volatile("cp.async.commit_group;" ::: "memory")
#define CP_WAIT(n)  asm volatile("cp.async.wait_group %0;" :: "n"(n) : "memory")

__device__ __forceinline__ void ldmx4(uint32_t* r, uint32_t addr) {
    asm volatile("ldmatrix.sync.aligned.m8n8.x4.shared.b16 {%0,%1,%2,%3}, [%4];"
                 : "=r"(r[0]), "=r"(r[1]), "=r"(r[2]), "=r"(r[3]) : "r"(addr));
}
__device__ __forceinline__ void ldmx4t(uint32_t* r, uint32_t addr) {
    asm volatile("ldmatrix.sync.aligned.m8n8.x4.trans.shared.b16 {%0,%1,%2,%3}, [%4];"
                 : "=r"(r[0]), "=r"(r[1]), "=r"(r[2]), "=r"(r[3]) : "r"(addr));
}
__device__ __forceinline__ void mma16816(float* d, const uint32_t* a,
                                         const uint32_t* b) {
    asm volatile(
        "mma.sync.aligned.m16n8k16.row.col.f32.f16.f16.f32 "
        "{%0,%1,%2,%3}, {%4,%5,%6,%7}, {%8,%9}, {%0,%1,%2,%3};"
        : "+f"(d[0]), "+f"(d[1]), "+f"(d[2]), "+f"(d[3])
        : "r"(a[0]), "r"(a[1]), "r"(a[2]), "r"(a[3]), "r"(b[0]), "r"(b[1]));
}

__device__ __forceinline__ void wh2(__half* p, size_t o, float a, float b) {
    *reinterpret_cast<__half2*>(p + o) = __floats2half2_rn(a, b);
}
__device__ __forceinline__ uint32_t ph2(float a, float b) {
    __half2 h = __floats2half2_rn(a, b);
    return *reinterpret_cast<uint32_t*>(&h);
}

// ---------------------------------------------------------------------------
// Conversion kernels (fp32 -> fp16)
// ---------------------------------------------------------------------------
__global__ __launch_bounds__(256) void convert_half(
    const float* __restrict__ in, __half* __restrict__ out)
{
    int i = (blockIdx.x * blockDim.x + threadIdx.x) << 2;
    float4 v = *(const float4*)(in + i);
    wh2(out, i, v.x, v.y);
    wh2(out, i + 2, v.z, v.w);
}

// Both weights transpose->fp16 in one launch.
__global__ __launch_bounds__(256) void transpose_half2(
    const float* __restrict__ Wq, const float* __restrict__ Wp,
    __half* __restrict__ qT, __half* __restrict__ pT)
{
    __shared__ float t[32][33];
    const int K = 1024;
    int bx = blockIdx.x;
    const float* W;
    __half* T;
    int N;
    if (bx < 96) { W = Wq; T = qT; N = 3072; }
    else         { W = Wp; T = pT; N = 1024; bx -= 96; }

    int n0 = bx << 5, k0 = blockIdx.y << 5;
    int tx = threadIdx.x, ty = threadIdx.y;   // 32 x 8
    #pragma unroll
    for (int i = 0; i < 4; i++)
        t[ty + 8 * i][tx] = W[(size_t)(k0 + ty + 8 * i) * N + n0 + tx];
    __syncthreads();
    #pragma unroll
    for (int i = 0; i < 4; i++) {
        size_t o = (size_t)(n0 + ty + 8 * i) * K + k0 + tx;
        T[o] = __float2half(t[tx][ty + 8 * i]);
    }
}

// ---------------------------------------------------------------------------
// fp16 GEMM via mma.sync. 128x128 CTA, 8 warps (2x4) of 64x32 tiles, BK=32.
// QKV variant fuses bias+RoPE+scatter into fp16 head buffers + f32 k/v out.
// ---------------------------------------------------------------------------
#define TILE_B 10240          // 128 rows * 80B
#define STAGE_B 20480         // A + B tiles

__device__ __forceinline__ void gemm_load_chunk(
    uint32_t sst,
    const __half* __restrict__ A, const __half* __restrict__ B,
    int bm, int bn, int K, int k0, int tid)
{
    #pragma unroll
    for (int j = 0; j < 2; j++) {
        int u = tid + (j << 8);              // 0..511
        int r = u >> 2;                      // 0..127
        int c16 = (u & 3) << 4;              // 0,16,32,48
        uint32_t d = sst + (uint32_t)r * 80 + c16;
        size_t ga = ((size_t)(bm + r) * K + k0) * 2 + c16;
        size_t gb = ((size_t)(bn + r) * K + k0) * 2 + c16;
        CP_ASYNC16(d,          (const char*)A + ga);
        CP_ASYNC16(d + TILE_B, (const char*)B + gb);
    }
}

template<bool QKV>
__global__ __launch_bounds__(256) void gemm_mma(
    const __half* __restrict__ A, const __half* __restrict__ B,
    const float* __restrict__ bias, float* __restrict__ C,
    int M, int N, int K,
    const float* __restrict__ cs, const float* __restrict__ sn,
    float* __restrict__ out_k, float* __restrict__ out_v,
    __half* __restrict__ qhx, __half* __restrict__ khx,
    __half* __restrict__ vhx)
{
    extern __shared__ char smem[];
    const uint32_t sb = smem_u32(smem);

    const int tid = threadIdx.x;
    const int wid = tid >> 5;
    const int lane = tid & 31;
    const int bm = blockIdx.y << 7, bn = blockIdx.x << 7;
    const int wm = (wid >> 2) << 6;
    const int wn = (wid & 3) << 5;

    float acc[4][4][4] = {};

    gemm_load_chunk(sb, A, B, bm, bn, K, 0, tid);
    CP_COMMIT();

    const int nchunk = K >> 5;
    for (int c = 0; c < nchunk; c++) {
        const uint32_t st = sb + (uint32_t)(c & 1) * STAGE_B;
        if (c + 1 < nchunk) {
            gemm_load_chunk(sb + (uint32_t)((c + 1) & 1) * STAGE_B,
                            A, B, bm, bn, K, (c + 1) << 5, tid);
            CP_COMMIT();
            CP_WAIT(1);
        } else {
            CP_WAIT(0);
        }
        __syncthreads();

        #pragma unroll
        for (int ks = 0; ks < 2; ks++) {
            const int kb = ks << 5;
            uint32_t af[4][4];
            #pragma unroll
            for (int mt = 0; mt < 4; mt++) {
                uint32_t addr = st
                    + (uint32_t)(wm + (mt << 4) + (lane & 15)) * 80
                    + kb + ((lane >> 4) << 4);
                ldmx4(af[mt], addr);
            }
            uint32_t bf[8];
            #pragma unroll
            for (int g = 0; g < 2; g++) {
                uint32_t nrow = wn + (g << 4) + (((lane >> 4) & 1) << 3)
                              + (lane & 7);
                uint32_t addr = st + TILE_B + nrow * 80 + kb
                              + (((lane >> 3) & 1) << 4);
                ldmx4(&bf[g << 2], addr);
            }
            #pragma unroll
            for (int mt = 0; mt < 4; mt++)
                #pragma unroll
                for (int nt = 0; nt < 4; nt++)
                    mma16816(acc[mt][nt], af[mt], &bf[nt << 1]);
        }
        __syncthreads();
    }

    const int r0 = bm + wm + (lane >> 2);
    const int cc0 = bn + wn + ((lane & 3) << 1);

    if (!QKV) {
        #pragma unroll
        for (int mt = 0; mt < 4; mt++) {
            #pragma unroll
            for (int nt = 0; nt < 4; nt++) {
                int col = cc0 + (nt << 3);
                float b0 = bias[col], b1 = bias[col + 1];
                int ra = r0 + (mt << 4);
                float2 v0 = make_float2(acc[mt][nt][0] + b0, acc[mt][nt][1] + b1);
                float2 v1 = make_float2(acc[mt][nt][2] + b0, acc[mt][nt][3] + b1);
                *(float2*)&C[(size_t)ra * N + col] = v0;
                *(float2*)&C[(size_t)(ra + 8) * N + col] = v1;
            }
        }
    } else {
        // fused bias + RoPE + head scatter (fp16 heads, f32 k/v outputs)
        const int region = bn >> 10;            // 0=q, 1=k, 2=v
        #pragma unroll
        for (int mt = 0; mt < 4; mt++) {
            #pragma unroll
            for (int rr = 0; rr < 2; rr++) {
                int row = r0 + (mt << 4) + (rr << 3);
                int s = row & 2047, bb = row >> 11;
                #pragma unroll
                for (int nt = 0; nt < 4; nt++) {
                    int col = cc0 + (nt << 3);
                    float2 bp = *(const float2*)&bias[col];
                    float v0 = acc[mt][nt][rr * 2]     + bp.x;
                    float v1 = acc[mt][nt][rr * 2 + 1] + bp.y;
                    int d = col - (region << 10);
                    int h = d >> 6, hd = d & 63;
                    size_t o = (((size_t)(bb * 16 + h)) * 2048 + s) * 64 + hd;
                    if (region == 2) {
                        wh2(vhx, o, v0, v1);
                        *(float2*)&out_v[o] = make_float2(v0, v1);
                    } else {
                        float2 cp = *(const float2*)&cs[s * 64 + hd];
                        float2 sp = *(const float2*)&sn[s * 64 + hd];
                        float rv0 = v0 * cp.x - v1 * sp.x;
                        float rv1 = v1 * cp.y + v0 * sp.y;
                        if (region == 0) {
                            wh2(qhx, o, rv0 * 0.125f, rv1 * 0.125f);
                        } else {
                            wh2(khx, o, rv0, rv1);
                            *(float2*)&out_k[o] = make_float2(rv0, rv1);
                        }
                    }
                }
            }
        }
    }
}

// ---------------------------------------------------------------------------
// Flash attention via fp16 mma.sync, single-pass.
// 128 threads, 4 warps, 64 q-rows/CTA; 32 kv tiles of 64.
// stage = K(9216) + V(9216) = 18432 B; double-buffered; Q reuses stage 1.
// ---------------------------------------------------------------------------
#define AST 144
#define ASTG 18432

__global__ __launch_bounds__(128, 4) void attn_mma(
    const __half* __restrict__ qh_, const __half* __restrict__ kh_,
    const __half* __restrict__ vh_, __half* __restrict__ yh_)
{
    extern __shared__ char smx[];
    const uint32_t sb = smem_u32(smx);
    const int tid = threadIdx.x, wid = tid >> 5, lane = tid & 31;
    const int bh = blockIdx.y, q0 = blockIdx.x << 6;     // 64 q-rows per CTA
    const uint32_t QH = sb + ASTG;                        // Q staging (= stage 1)

    const size_t hbase = (size_t)bh * 2048 * 64;
    const char* kh = (const char*)(kh_ + hbase);
    const char* vh = (const char*)(vh_ + hbase);

    // Q -> smem (64 rows x 128B)
    {
        const char* qhg = (const char*)(qh_ + hbase + (size_t)q0 * 64);
        #pragma unroll
        for (int j = 0; j < 4; j++) {
            int u = tid + (j << 7); int r = u >> 3; int c = (u & 7) << 4;
            CP_ASYNC16(QH + r * AST + c, qhg + r * 128 + c);
        }
        CP_COMMIT();
    }
    // tile 0 -> stage 0
    {
        #pragma unroll
        for (int j = 0; j < 4; j++) {
            int u = tid + (j << 7); int r = u >> 3; int c = (u & 7) << 4;
            uint32_t d = sb + r * AST + c;
            int go = r * 128 + c;
            CP_ASYNC16(d, kh + go);
            CP_ASYNC16(d + 9216, vh + go);
        }
        CP_COMMIT();
    }
    CP_WAIT(1);
    __syncthreads();

    // Q fragments (registers for whole kernel). Warp owns rows wid*16..+15.
    uint32_t qf[4][4];
    #pragma unroll
    for (int kt = 0; kt < 4; kt++) {
        uint32_t a = QH + (uint32_t)((wid << 4) + (lane & 15)) * AST
                   + (kt << 5) + ((lane >> 4) << 4);
        ldmx4(qf[kt], a);
    }
    __syncthreads();   // Q region now reusable as stage 1

    float m0 = -1e30f, m1 = -1e30f, l0 = 0.f, l1 = 0.f;
    float o[8][4] = {};

    for (int t = 0; t < 32; t++) {
        const uint32_t st = sb + (uint32_t)(t & 1) * ASTG;
        if (t + 1 < 32) {
            uint32_t dstg = sb + (uint32_t)((t + 1) & 1) * ASTG;
            size_t tb = (size_t)(t + 1) * 64 * 128;
            #pragma unroll
            for (int j = 0; j < 4; j++) {
                int u = tid + (j << 7); int r = u >> 3; int c = (u & 7) << 4;
                uint32_t d = dstg + r * AST + c;
                size_t go = tb + r * 128 + c;
                CP_ASYNC16(d, kh + go);
                CP_ASYNC16(d + 9216, vh + go);
            }
            CP_COMMIT();
            CP_WAIT(1);
        } else {
            CP_WAIT(0);
        }
        __syncthreads();

        // S = Q K^T (single-pass fp16)
        float sacc[8][4] = {};
        #pragma unroll
        for (int kt = 0; kt < 4; kt++) {
            #pragma unroll
            for (int g = 0; g < 4; g++) {
                uint32_t na = st
                    + (uint32_t)((g << 4) + (((lane >> 4) & 1) << 3) + (lane & 7)) * AST
                    + (kt << 5) + (((lane >> 3) & 1) << 4);
                uint32_t kf[4];
                ldmx4(kf, na);
                mma16816(sacc[2 * g],     qf[kt], &kf[0]);
                mma16816(sacc[2 * g + 1], qf[kt], &kf[2]);
            }
        }

        // online softmax (rows r0 = lane/4, r1 = r0+8)
        float mx0 = -1e30f, mx1 = -1e30f;
        #pragma unroll
        for (int n = 0; n < 8; n++) {
            mx0 = fmaxf(mx0, fmaxf(sacc[n][0], sacc[n][1]));
            mx1 = fmaxf(mx1, fmaxf(sacc[n][2], sacc[n][3]));
        }
        mx0 = fmaxf(mx0, __shfl_xor_sync(0xffffffffu, mx0, 1));
        mx0 = fmaxf(mx0, __shfl_xor_sync(0xffffffffu, mx0, 2));
        mx1 = fmaxf(mx1, __shfl_xor_sync(0xffffffffu, mx1, 1));
        mx1 = fmaxf(mx1, __shfl_xor_sync(0xffffffffu, mx1, 2));
        float nm0 = fmaxf(m0, mx0), nm1 = fmaxf(m1, mx1);
        float al0 = __expf(m0 - nm0), al1 = __expf(m1 - nm1);
        float rs0 = 0.f, rs1 = 0.f;
        #pragma unroll
        for (int n = 0; n < 8; n++) {
            sacc[n][0] = __expf(sacc[n][0] - nm0);
            sacc[n][1] = __expf(sacc[n][1] - nm0);
            sacc[n][2] = __expf(sacc[n][2] - nm1);
            sacc[n][3] = __expf(sacc[n][3] - nm1);
            rs0 += sacc[n][0] + sacc[n][1];
            rs1 += sacc[n][2] + sacc[n][3];
        }
        rs0 += __shfl_xor_sync(0xffffffffu, rs0, 1);
        rs0 += __shfl_xor_sync(0xffffffffu, rs0, 2);
        rs1 += __shfl_xor_sync(0xffffffffu, rs1, 1);
        rs1 += __shfl_xor_sync(0xffffffffu, rs1, 2);
        l0 = l0 * al0 + rs0; l1 = l1 * al1 + rs1;
        m0 = nm0; m1 = nm1;
        #pragma unroll
        for (int n = 0; n < 8; n++) {
            o[n][0] *= al0; o[n][1] *= al0;
            o[n][2] *= al1; o[n][3] *= al1;
        }

        // O += P V (single-pass fp16; P packed in registers)
        #pragma unroll
        for (int kt = 0; kt < 4; kt++) {
            uint32_t ph[4];
            ph[0] = ph2(sacc[2 * kt][0],     sacc[2 * kt][1]);
            ph[1] = ph2(sacc[2 * kt][2],     sacc[2 * kt][3]);
            ph[2] = ph2(sacc[2 * kt + 1][0], sacc[2 * kt + 1][1]);
            ph[3] = ph2(sacc[2 * kt + 1][2], sacc[2 * kt + 1][3]);
            #pragma unroll
            for (int g = 0; g < 4; g++) {
                uint32_t va = st + 9216
                    + (uint32_t)((kt << 4) + (lane & 7) + (((lane >> 3) & 1) << 3)) * AST
                    + (((g << 4) + (((lane >> 4) & 1) << 3)) << 1);
                uint32_t vf[4];
                ldmx4t(vf, va);
                mma16816(o[2 * g],     ph, &vf[0]);
                mma16816(o[2 * g + 1], ph, &vf[2]);
            }
        }
        __syncthreads();
    }

    // epilogue: y = O / l -> fp16 (proj input)
    float il0 = 1.f / l0, il1 = 1.f / l1;
    const int b = bh >> 4, h = bh & 15;
    const int r0 = b * 2048 + q0 + (wid << 4) + (lane >> 2);
    const int c0 = h * 64 + ((lane & 3) << 1);
    #pragma unroll
    for (int n = 0; n < 8; n++) {
        size_t o0 = (size_t)r0 * 1024 + c0 + (n << 3);
        wh2(yh_, o0, o[n][0] * il0, o[n][1] * il0);
        wh2(yh_, o0 + 8 * 1024, o[n][2] * il1, o[n][3] * il1);
    }
}

// ---------------------------------------------------------------------------
extern "C" void kernel_launch(void* const* d_in, const int* in_sizes, int n_in,
                              void* d_out, int out_size)
{
    const float* x     = (const float*)d_in[0];
    const float* cs    = (const float*)d_in[1];
    const float* sn    = (const float*)d_in[2];
    const float* Wqkv  = (const float*)d_in[3];
    const float* bqkv  = (const float*)d_in[4];
    const float* Wproj = (const float*)d_in[5];
    const float* bproj = (const float*)d_in[6];

    float* out   = (float*)d_out;
    float* out_y = out;
    float* out_k = out + (size_t)2 * 2048 * 1024;
    float* out_v = out_k + (size_t)2 * 16 * 2048 * 64;

    __half *xh, *wqt, *wpt, *yh, *qh, *kh, *vh;
    cudaGetSymbolAddress((void**)&xh, g_xh);
    cudaGetSymbolAddress((void**)&wqt, g_wqt);
    cudaGetSymbolAddress((void**)&wpt, g_wpt);
    cudaGetSymbolAddress((void**)&yh, g_yh);
    cudaGetSymbolAddress((void**)&qh, g_qh);
    cudaGetSymbolAddress((void**)&kh, g_kh);
    cudaGetSymbolAddress((void**)&vh, g_vh);

    const int gemm_smem = 2 * STAGE_B;   // 40960
    cudaFuncSetAttribute(gemm_mma<true>,
                         cudaFuncAttributeMaxDynamicSharedMemorySize, gemm_smem);
    cudaFuncSetAttribute(gemm_mma<false>,
                         cudaFuncAttributeMaxDynamicSharedMemorySize, gemm_smem);
    const int attn_smem = 2 * ASTG;      // 36864
    cudaFuncSetAttribute(attn_mma,
                         cudaFuncAttributeMaxDynamicSharedMemorySize, attn_smem);

    // 0) fp16 conversions
    convert_half<<<4096, 256>>>(x, xh);
    transpose_half2<<<dim3(128, 32), dim3(32, 8)>>>(Wqkv, Wproj, wqt, wpt);

    // 1) QKV GEMM + fused bias/RoPE/scatter
    gemm_mma<true><<<dim3(24, 32), 256, gemm_smem>>>(
        xh, wqt, bqkv, nullptr, 4096, 3072, 1024,
        cs, sn, out_k, out_v, qh, kh, vh);

    // 2) Attention -> y fp16
    attn_mma<<<dim3(32, 32), 128, attn_smem>>>(qh, kh, vh, yh);

    // 3) Projection
    gemm_mma<false><<<dim3(8, 32), 256, gemm_smem>>>(
        yh, wpt, bproj, out_y, 4096, 1024, 1024,
        nullptr, nullptr, nullptr, nullptr, nullptr, nullptr, nullptr);
}

// round 12
// speedup vs baseline: 2.4871x; 1.0536x over previous
#include <cuda_runtime.h>
#include <cuda_fp16.h>
#include <math.h>
#include <stdint.h>

// B=2, S=2048, D=1024, H=16, HD=64

// ---------------- scratch (device globals, fp16) ----------------
__device__ __half g_xh[4194304];        // x fp16
__device__ __half g_wqt[3145728];       // Wqkv^T fp16
__device__ __half g_wpt[1048576];       // Wproj^T fp16
__device__ __half g_yh[4194304];        // attn out fp16
__device__ __half g_qh[4194304];        // q heads (rot, scaled by 0.125*log2e)
__device__ __half g_kh[4194304];        // k heads fp16
__device__ __half g_vh[4194304];        // v heads fp16

// ---------------- helpers ----------------
__device__ __forceinline__ uint32_t smem_u32(const void* p) {
    uint32_t a;
    asm("{ .reg .u64 t; cvta.to.shared.u64 t, %1; cvt.u32.u64 %0, t; }"
        : "=r"(a) : "l"(p));
    return a;
}

#define CP_ASYNC16(dst, src) \
    asm volatile("cp.async.cg.shared.global [%0], [%1], 16;" \
                 :: "r"(dst), "l"(src))
#define CP_COMMIT() asm volatile("cp.async.commit_group;" ::: "memory")
#define CP_WAIT(n)  asm volatile("cp.async.wait_group %0;" :: "n"(n) : "memory")

__device__ __forceinline__ void ldmx4(uint32_t* r, uint32_t addr) {
    asm volatile("ldmatrix.sync.aligned.m8n8.x4.shared.b16 {%0,%1,%2,%3}, [%4];"
                 : "=r"(r[0]), "=r"(r[1]), "=r"(r[2]), "=r"(r[3]) : "r"(addr));
}
__device__ __forceinline__ void ldmx4t(uint32_t* r, uint32_t addr) {
    asm volatile("ldmatrix.sync.aligned.m8n8.x4.trans.shared.b16 {%0,%1,%2,%3}, [%4];"
                 : "=r"(r[0]), "=r"(r[1]), "=r"(r[2]), "=r"(r[3]) : "r"(addr));
}
__device__ __forceinline__ void mma16816(float* d, const uint32_t* a,
                                         const uint32_t* b) {
    asm volatile(
        "mma.sync.aligned.m16n8k16.row.col.f32.f16.f16.f32 "
        "{%0,%1,%2,%3}, {%4,%5,%6,%7}, {%8,%9}, {%0,%1,%2,%3};"
        : "+f"(d[0]), "+f"(d[1]), "+f"(d[2]), "+f"(d[3])
        : "r"(a[0]), "r"(a[1]), "r"(a[2]), "r"(a[3]), "r"(b[0]), "r"(b[1]));
}

__device__ __forceinline__ float ex2(float x) {
    float y;
    asm("ex2.approx.ftz.f32 %0, %1;" : "=f"(y) : "f"(x));
    return y;
}

__device__ __forceinline__ void wh2(__half* p, size_t o, float a, float b) {
    *reinterpret_cast<__half2*>(p + o) = __floats2half2_rn(a, b);
}
__device__ __forceinline__ uint32_t ph2(float a, float b) {
    __half2 h = __floats2half2_rn(a, b);
    return *reinterpret_cast<uint32_t*>(&h);
}

// ---------------------------------------------------------------------------
// Conversion kernels (fp32 -> fp16)
// ---------------------------------------------------------------------------
__global__ __launch_bounds__(256) void convert_half(
    const float* __restrict__ in, __half* __restrict__ out)
{
    int i = (blockIdx.x * blockDim.x + threadIdx.x) << 2;
    float4 v = *(const float4*)(in + i);
    wh2(out, i, v.x, v.y);
    wh2(out, i + 2, v.z, v.w);
}

__global__ __launch_bounds__(256) void transpose_half2(
    const float* __restrict__ Wq, const float* __restrict__ Wp,
    __half* __restrict__ qT, __half* __restrict__ pT)
{
    __shared__ float t[32][33];
    const int K = 1024;
    int bx = blockIdx.x;
    const float* W;
    __half* T;
    int N;
    if (bx < 96) { W = Wq; T = qT; N = 3072; }
    else         { W = Wp; T = pT; N = 1024; bx -= 96; }

    int n0 = bx << 5, k0 = blockIdx.y << 5;
    int tx = threadIdx.x, ty = threadIdx.y;   // 32 x 8
    #pragma unroll
    for (int i = 0; i < 4; i++)
        t[ty + 8 * i][tx] = W[(size_t)(k0 + ty + 8 * i) * N + n0 + tx];
    __syncthreads();
    #pragma unroll
    for (int i = 0; i < 4; i++) {
        size_t o = (size_t)(n0 + ty + 8 * i) * K + k0 + tx;
        T[o] = __float2half(t[tx][ty + 8 * i]);
    }
}

// ---------------------------------------------------------------------------
// fp16 GEMM via mma.sync. 128x128 CTA, 8 warps (2x4) of 64x32 tiles, BK=32.
// 3-stage cp.async pipeline. QKV variant fuses bias+RoPE+scatter.
// ---------------------------------------------------------------------------
#define TILE_B 10240          // 128 rows * 80B
#define STAGE_B 20480         // A + B tiles
#define QSCALE 0.1803368801111204f   // 0.125 * log2(e)

__device__ __forceinline__ void gemm_load_chunk(
    uint32_t sst,
    const __half* __restrict__ A, const __half* __restrict__ B,
    int bm, int bn, int K, int k0, int tid)
{
    #pragma unroll
    for (int j = 0; j < 2; j++) {
        int u = tid + (j << 8);
        int r = u >> 2;
        int c16 = (u & 3) << 4;
        uint32_t d = sst + (uint32_t)r * 80 + c16;
        size_t ga = ((size_t)(bm + r) * K + k0) * 2 + c16;
        size_t gb = ((size_t)(bn + r) * K + k0) * 2 + c16;
        CP_ASYNC16(d,          (const char*)A + ga);
        CP_ASYNC16(d + TILE_B, (const char*)B + gb);
    }
}

template<bool QKV>
__global__ __launch_bounds__(256) void gemm_mma(
    const __half* __restrict__ A, const __half* __restrict__ B,
    const float* __restrict__ bias, float* __restrict__ C,
    int M, int N, int K,
    const float* __restrict__ cs, const float* __restrict__ sn,
    float* __restrict__ out_k, float* __restrict__ out_v,
    __half* __restrict__ qhx, __half* __restrict__ khx,
    __half* __restrict__ vhx)
{
    extern __shared__ char smem[];
    const uint32_t sb = smem_u32(smem);

    const int tid = threadIdx.x;
    const int wid = tid >> 5;
    const int lane = tid & 31;
    const int bm = blockIdx.y << 7, bn = blockIdx.x << 7;
    const int wm = (wid >> 2) << 6;
    const int wn = (wid & 3) << 5;

    float acc[4][4][4] = {};

    // prefetch chunks 0,1
    gemm_load_chunk(sb, A, B, bm, bn, K, 0, tid);
    CP_COMMIT();
    gemm_load_chunk(sb + STAGE_B, A, B, bm, bn, K, 32, tid);
    CP_COMMIT();

    const int nchunk = K >> 5;
    int s3 = 0;                       // c % 3
    for (int c = 0; c < nchunk; c++) {
        const uint32_t st = sb + (uint32_t)s3 * STAGE_B;
        if (c + 1 < nchunk) { CP_WAIT(1); } else { CP_WAIT(0); }
        __syncthreads();
        if (c + 2 < nchunk) {
            int ns = s3 + 2; if (ns >= 3) ns -= 3;
            gemm_load_chunk(sb + (uint32_t)ns * STAGE_B,
                            A, B, bm, bn, K, (c + 2) << 5, tid);
            CP_COMMIT();
        }

        #pragma unroll
        for (int ks = 0; ks < 2; ks++) {
            const int kb = ks << 5;
            uint32_t af[4][4];
            #pragma unroll
            for (int mt = 0; mt < 4; mt++) {
                uint32_t addr = st
                    + (uint32_t)(wm + (mt << 4) + (lane & 15)) * 80
                    + kb + ((lane >> 4) << 4);
                ldmx4(af[mt], addr);
            }
            uint32_t bf[8];
            #pragma unroll
            for (int g = 0; g < 2; g++) {
                uint32_t nrow = wn + (g << 4) + (((lane >> 4) & 1) << 3)
                              + (lane & 7);
                uint32_t addr = st + TILE_B + nrow * 80 + kb
                              + (((lane >> 3) & 1) << 4);
                ldmx4(&bf[g << 2], addr);
            }
            #pragma unroll
            for (int mt = 0; mt < 4; mt++)
                #pragma unroll
                for (int nt = 0; nt < 4; nt++)
                    mma16816(acc[mt][nt], af[mt], &bf[nt << 1]);
        }
        if (++s3 == 3) s3 = 0;
    }

    const int r0 = bm + wm + (lane >> 2);
    const int cc0 = bn + wn + ((lane & 3) << 1);

    if (!QKV) {
        #pragma unroll
        for (int mt = 0; mt < 4; mt++) {
            #pragma unroll
            for (int nt = 0; nt < 4; nt++) {
                int col = cc0 + (nt << 3);
                float b0 = bias[col], b1 = bias[col + 1];
                int ra = r0 + (mt << 4);
                float2 v0 = make_float2(acc[mt][nt][0] + b0, acc[mt][nt][1] + b1);
                float2 v1 = make_float2(acc[mt][nt][2] + b0, acc[mt][nt][3] + b1);
                *(float2*)&C[(size_t)ra * N + col] = v0;
                *(float2*)&C[(size_t)(ra + 8) * N + col] = v1;
            }
        }
    } else {
        const int region = bn >> 10;            // 0=q, 1=k, 2=v
        #pragma unroll
        for (int mt = 0; mt < 4; mt++) {
            #pragma unroll
            for (int rr = 0; rr < 2; rr++) {
                int row = r0 + (mt << 4) + (rr << 3);
                int s = row & 2047, bb = row >> 11;
                #pragma unroll
                for (int nt = 0; nt < 4; nt++) {
                    int col = cc0 + (nt << 3);
                    float2 bp = *(const float2*)&bias[col];
                    float v0 = acc[mt][nt][rr * 2]     + bp.x;
                    float v1 = acc[mt][nt][rr * 2 + 1] + bp.y;
                    int d = col - (region << 10);
                    int h = d >> 6, hd = d & 63;
                    size_t o = (((size_t)(bb * 16 + h)) * 2048 + s) * 64 + hd;
                    if (region == 2) {
                        wh2(vhx, o, v0, v1);
                        *(float2*)&out_v[o] = make_float2(v0, v1);
                    } else {
                        float2 cp = *(const float2*)&cs[s * 64 + hd];
                        float2 sp = *(const float2*)&sn[s * 64 + hd];
                        float rv0 = v0 * cp.x - v1 * sp.x;
                        float rv1 = v1 * cp.y + v0 * sp.y;
                        if (region == 0) {
                            wh2(qhx, o, rv0 * QSCALE, rv1 * QSCALE);
                        } else {
                            wh2(khx, o, rv0, rv1);
                            *(float2*)&out_k[o] = make_float2(rv0, rv1);
                        }
                    }
                }
            }
        }
    }
}

// ---------------------------------------------------------------------------
// Flash attention via fp16 mma.sync, single-pass, exp2-domain softmax.
// 128 threads, 4 warps, 64 q-rows/CTA; 32 kv tiles of 64.
// ---------------------------------------------------------------------------
#define AST 144
#define ASTG 18432

__global__ __launch_bounds__(128, 4) void attn_mma(
    const __half* __restrict__ qh_, const __half* __restrict__ kh_,
    const __half* __restrict__ vh_, __half* __restrict__ yh_)
{
    extern __shared__ char smx[];
    const uint32_t sb = smem_u32(smx);
    const int tid = threadIdx.x, wid = tid >> 5, lane = tid & 31;
    const int bh = blockIdx.y, q0 = blockIdx.x << 6;
    const uint32_t QH = sb + ASTG;

    const size_t hbase = (size_t)bh * 2048 * 64;
    const char* kh = (const char*)(kh_ + hbase);
    const char* vh = (const char*)(vh_ + hbase);

    {
        const char* qhg = (const char*)(qh_ + hbase + (size_t)q0 * 64);
        #pragma unroll
        for (int j = 0; j < 4; j++) {
            int u = tid + (j << 7); int r = u >> 3; int c = (u & 7) << 4;
            CP_ASYNC16(QH + r * AST + c, qhg + r * 128 + c);
        }
        CP_COMMIT();
    }
    {
        #pragma unroll
        for (int j = 0; j < 4; j++) {
            int u = tid + (j << 7); int r = u >> 3; int c = (u & 7) << 4;
            uint32_t d = sb + r * AST + c;
            int go = r * 128 + c;
            CP_ASYNC16(d, kh + go);
            CP_ASYNC16(d + 9216, vh + go);
        }
        CP_COMMIT();
    }
    CP_WAIT(1);
    __syncthreads();

    uint32_t qf[4][4];
    #pragma unroll
    for (int kt = 0; kt < 4; kt++) {
        uint32_t a = QH + (uint32_t)((wid << 4) + (lane & 15)) * AST
                   + (kt << 5) + ((lane >> 4) << 4);
        ldmx4(qf[kt], a);
    }
    __syncthreads();

    float m0 = -1e30f, m1 = -1e30f, l0 = 0.f, l1 = 0.f;
    float o[8][4] = {};

    for (int t = 0; t < 32; t++) {
        const uint32_t st = sb + (uint32_t)(t & 1) * ASTG;
        if (t + 1 < 32) {
            uint32_t dstg = sb + (uint32_t)((t + 1) & 1) * ASTG;
            size_t tb = (size_t)(t + 1) * 64 * 128;
            #pragma unroll
            for (int j = 0; j < 4; j++) {
                int u = tid + (j << 7); int r = u >> 3; int c = (u & 7) << 4;
                uint32_t d = dstg + r * AST + c;
                size_t go = tb + r * 128 + c;
                CP_ASYNC16(d, kh + go);
                CP_ASYNC16(d + 9216, vh + go);
            }
            CP_COMMIT();
            CP_WAIT(1);
        } else {
            CP_WAIT(0);
        }
        __syncthreads();

        // S (log2 domain; q pre-scaled by 0.125*log2e)
        float sacc[8][4] = {};
        #pragma unroll
        for (int kt = 0; kt < 4; kt++) {
            #pragma unroll
            for (int g = 0; g < 4; g++) {
                uint32_t na = st
                    + (uint32_t)((g << 4) + (((lane >> 4) & 1) << 3) + (lane & 7)) * AST
                    + (kt << 5) + (((lane >> 3) & 1) << 4);
                uint32_t kf[4];
                ldmx4(kf, na);
                mma16816(sacc[2 * g],     qf[kt], &kf[0]);
                mma16816(sacc[2 * g + 1], qf[kt], &kf[2]);
            }
        }

        // online softmax in exp2 domain
        float mx0 = -1e30f, mx1 = -1e30f;
        #pragma unroll
        for (int n = 0; n < 8; n++) {
            mx0 = fmaxf(mx0, fmaxf(sacc[n][0], sacc[n][1]));
            mx1 = fmaxf(mx1, fmaxf(sacc[n][2], sacc[n][3]));
        }
        mx0 = fmaxf(mx0, __shfl_xor_sync(0xffffffffu, mx0, 1));
        mx0 = fmaxf(mx0, __shfl_xor_sync(0xffffffffu, mx0, 2));
        mx1 = fmaxf(mx1, __shfl_xor_sync(0xffffffffu, mx1, 1));
        mx1 = fmaxf(mx1, __shfl_xor_sync(0xffffffffu, mx1, 2));
        float nm0 = fmaxf(m0, mx0), nm1 = fmaxf(m1, mx1);
        float al0 = ex2(m0 - nm0), al1 = ex2(m1 - nm1);
        float rs0 = 0.f, rs1 = 0.f;
        #pragma unroll
        for (int n = 0; n < 8; n++) {
            sacc[n][0] = ex2(sacc[n][0] - nm0);
            sacc[n][1] = ex2(sacc[n][1] - nm0);
            sacc[n][2] = ex2(sacc[n][2] - nm1);
            sacc[n][3] = ex2(sacc[n][3] - nm1);
            rs0 += sacc[n][0] + sacc[n][1];
            rs1 += sacc[n][2] + sacc[n][3];
        }
        rs0 += __shfl_xor_sync(0xffffffffu, rs0, 1);
        rs0 += __shfl_xor_sync(0xffffffffu, rs0, 2);
        rs1 += __shfl_xor_sync(0xffffffffu, rs1, 1);
        rs1 += __shfl_xor_sync(0xffffffffu, rs1, 2);
        l0 = l0 * al0 + rs0; l1 = l1 * al1 + rs1;
        m0 = nm0; m1 = nm1;
        #pragma unroll
        for (int n = 0; n < 8; n++) {
            o[n][0] *= al0; o[n][1] *= al0;
            o[n][2] *= al1; o[n][3] *= al1;
        }

        // O += P V
        #pragma unroll
        for (int kt = 0; kt < 4; kt++) {
            uint32_t ph[4];
            ph[0] = ph2(sacc[2 * kt][0],     sacc[2 * kt][1]);
            ph[1] = ph2(sacc[2 * kt][2],     sacc[2 * kt][3]);
            ph[2] = ph2(sacc[2 * kt + 1][0], sacc[2 * kt + 1][1]);
            ph[3] = ph2(sacc[2 * kt + 1][2], sacc[2 * kt + 1][3]);
            #pragma unroll
            for (int g = 0; g < 4; g++) {
                uint32_t va = st + 9216
                    + (uint32_t)((kt << 4) + (lane & 7) + (((lane >> 3) & 1) << 3)) * AST
                    + (((g << 4) + (((lane >> 4) & 1) << 3)) << 1);
                uint32_t vf[4];
                ldmx4t(vf, va);
                mma16816(o[2 * g],     ph, &vf[0]);
                mma16816(o[2 * g + 1], ph, &vf[2]);
            }
        }
        __syncthreads();
    }

    float il0 = 1.f / l0, il1 = 1.f / l1;
    const int b = bh >> 4, h = bh & 15;
    const int r0 = b * 2048 + q0 + (wid << 4) + (lane >> 2);
    const int c0 = h * 64 + ((lane & 3) << 1);
    #pragma unroll
    for (int n = 0; n < 8; n++) {
        size_t o0 = (size_t)r0 * 1024 + c0 + (n << 3);
        wh2(yh_, o0, o[n][0] * il0, o[n][1] * il0);
        wh2(yh_, o0 + 8 * 1024, o[n][2] * il1, o[n][3] * il1);
    }
}

// ---------------------------------------------------------------------------
extern "C" void kernel_launch(void* const* d_in, const int* in_sizes, int n_in,
                              void* d_out, int out_size)
{
    const float* x     = (const float*)d_in[0];
    const float* cs    = (const float*)d_in[1];
    const float* sn    = (const float*)d_in[2];
    const float* Wqkv  = (const float*)d_in[3];
    const float* bqkv  = (const float*)d_in[4];
    const float* Wproj = (const float*)d_in[5];
    const float* bproj = (const float*)d_in[6];

    float* out   = (float*)d_out;
    float* out_y = out;
    float* out_k = out + (size_t)2 * 2048 * 1024;
    float* out_v = out_k + (size_t)2 * 16 * 2048 * 64;

    __half *xh, *wqt, *wpt, *yh, *qh, *kh, *vh;
    cudaGetSymbolAddress((void**)&xh, g_xh);
    cudaGetSymbolAddress((void**)&wqt, g_wqt);
    cudaGetSymbolAddress((void**)&wpt, g_wpt);
    cudaGetSymbolAddress((void**)&yh, g_yh);
    cudaGetSymbolAddress((void**)&qh, g_qh);
    cudaGetSymbolAddress((void**)&kh, g_kh);
    cudaGetSymbolAddress((void**)&vh, g_vh);

    const int gemm_smem = 3 * STAGE_B;   // 61440
    cudaFuncSetAttribute(gemm_mma<true>,
                         cudaFuncAttributeMaxDynamicSharedMemorySize, gemm_smem);
    cudaFuncSetAttribute(gemm_mma<false>,
                         cudaFuncAttributeMaxDynamicSharedMemorySize, gemm_smem);
    const int attn_smem = 2 * ASTG;      // 36864
    cudaFuncSetAttribute(attn_mma,
                         cudaFuncAttributeMaxDynamicSharedMemorySize, attn_smem);

    // 0) fp16 conversions
    convert_half<<<4096, 256>>>(x, xh);
    transpose_half2<<<dim3(128, 32), dim3(32, 8)>>>(Wqkv, Wproj, wqt, wpt);

    // 1) QKV GEMM + fused bias/RoPE/scatter
    gemm_mma<true><<<dim3(24, 32), 256, gemm_smem>>>(
        xh, wqt, bqkv, nullptr, 4096, 3072, 1024,
        cs, sn, out_k, out_v, qh, kh, vh);

    // 2) Attention -> y fp16
    attn_mma<<<dim3(32, 32), 128, attn_smem>>>(qh, kh, vh, yh);

    // 3) Projection
    gemm_mma<false><<<dim3(8, 32), 256, gemm_smem>>>(
        yh, wpt, bproj, out_y, 4096, 1024, 1024,
        nullptr, nullptr, nullptr, nullptr, nullptr, nullptr, nullptr);
}